// round 1
// baseline (speedup 1.0000x reference)
#include <cuda_runtime.h>
#include <math.h>

// ---------------------------------------------------------------------------
// Problem constants
// ---------------------------------------------------------------------------
#define BROWS 1024      // batch
#define CDICT 10000     // dictionary atoms
#define DM    512       // embedding dim
#define RHO_F 5.0f
#define THR_F 0.002f    // lam / rho = 0.01 / 5
#define EPS_F 1e-12f
#define ADMM_ITERS 100
#define NS_ITERS 12
#define KSPLIT 5        // split-K slices for K=10000 GEMMs (2000 per slice)

// ---------------------------------------------------------------------------
// Scratch (static device globals -- no cudaMalloc allowed)
// ---------------------------------------------------------------------------
__device__ float g_Q[(size_t)BROWS * CDICT];   // Aty, then q
__device__ float g_V[(size_t)BROWS * CDICT];   // v = z - u  (z on last iter)
__device__ float g_U[(size_t)BROWS * CDICT];   // u
__device__ float g_E[(size_t)DM * CDICT];      // E = G^{-1} D^T
__device__ float g_P[(size_t)KSPLIT * BROWS * DM]; // split-K partials (reused)
__device__ float g_W[(size_t)BROWS * DM];      // T0 / w / recon_raw
__device__ float g_Y[(size_t)BROWS * DM];      // centered inputs
__device__ float g_G[DM * DM];
__device__ float g_XA[DM * DM];
__device__ float g_XB[DM * DM];
__device__ float g_T[DM * DM];
__device__ float g_ninf;

// ---------------------------------------------------------------------------
// Generic tiled SGEMM: C[M,N] += opA(A)[M,K] * opB(B)[K,N]
//   TA: A element (m,k) = A[k*lda + m]   (else A[m*lda + k])
//   TB: B element (k,n) = B[n*ldb + k]   (else B[k*ldb + n])
// blockIdx.z = split-K slice (EPI==0 only): writes partial to C + z*M*ldc
// EPI 0: plain store (partial)
// EPI 1: C[idx] = (Qp[idx] - acc) / rho              (q precompute, in-place on Q)
// EPI 2: ADMM fused update:
//        x = Qp + Vp - acc; z = max(x+Up-thr,0); u' = Up+x-z;
//        Uout = u'; C = is_last ? z : (2z - Up - x)
// ---------------------------------------------------------------------------
#define BM 128
#define BN 128
#define BKK 16

template<bool TA, bool TB, int EPI>
__global__ void __launch_bounds__(256, 2)
gemm_kernel(const float* __restrict__ A, const float* __restrict__ B,
            float* __restrict__ C,
            int M, int N, int Kslice, int lda, int ldb, int ldc,
            const float* __restrict__ Qp, const float* __restrict__ Vp,
            const float* __restrict__ Up, float* __restrict__ Uout,
            int is_last)
{
    __shared__ float As[BKK][BM + 4];
    __shared__ float Bs[BKK][BN + 4];

    const int tid = threadIdx.x;
    const int tx  = tid & 15;
    const int ty  = tid >> 4;
    const int m0  = blockIdx.y * BM;
    const int n0  = blockIdx.x * BN;

    const long k0 = (long)blockIdx.z * Kslice;
    if (TA) A += k0 * lda; else A += k0;
    if (TB) B += k0;       else B += k0 * ldb;
    if (EPI == 0) C += (long)blockIdx.z * (long)M * ldc;

    float acc[8][8];
#pragma unroll
    for (int i = 0; i < 8; ++i)
#pragma unroll
        for (int j = 0; j < 8; ++j) acc[i][j] = 0.0f;

    const int nk = Kslice / BKK;
#pragma unroll 1
    for (int kt = 0; kt < nk; ++kt) {
        const int kbase = kt * BKK;
        // ---- load A tile ----
        if (!TA) {
#pragma unroll
            for (int p = 0; p < 2; ++p) {
                const int row = p * 64 + (tid >> 2);
                const int c4  = (tid & 3) * 4;
                float4 v = *(const float4*)&A[(long)(m0 + row) * lda + kbase + c4];
                As[c4 + 0][row] = v.x; As[c4 + 1][row] = v.y;
                As[c4 + 2][row] = v.z; As[c4 + 3][row] = v.w;
            }
        } else {
#pragma unroll
            for (int p = 0; p < 2; ++p) {
                const int kr = p * 8 + (tid >> 5);
                const int m4 = (tid & 31) * 4;
                float4 v = *(const float4*)&A[(long)(kbase + kr) * lda + m0 + m4];
                *(float4*)&As[kr][m4] = v;
            }
        }
        // ---- load B tile ----
        if (!TB) {
#pragma unroll
            for (int p = 0; p < 2; ++p) {
                const int kr  = p * 8 + (tid >> 5);
                const int nn4 = (tid & 31) * 4;
                const int gn  = n0 + nn4;
                float4 v = make_float4(0.f, 0.f, 0.f, 0.f);
                if (gn < N) v = *(const float4*)&B[(long)(kbase + kr) * ldb + gn];
                *(float4*)&Bs[kr][nn4] = v;
            }
        } else {
#pragma unroll
            for (int p = 0; p < 2; ++p) {
                const int nrow = p * 64 + (tid >> 2);
                const int c4   = (tid & 3) * 4;
                const int gn   = n0 + nrow;
                float4 v = make_float4(0.f, 0.f, 0.f, 0.f);
                if (gn < N) v = *(const float4*)&B[(long)gn * ldb + kbase + c4];
                Bs[c4 + 0][nrow] = v.x; Bs[c4 + 1][nrow] = v.y;
                Bs[c4 + 2][nrow] = v.z; Bs[c4 + 3][nrow] = v.w;
            }
        }
        __syncthreads();
        // ---- FMA ----
#pragma unroll
        for (int kk = 0; kk < BKK; ++kk) {
            float a[8], b[8];
            *(float4*)&a[0] = *(const float4*)&As[kk][ty * 4];
            *(float4*)&a[4] = *(const float4*)&As[kk][64 + ty * 4];
            *(float4*)&b[0] = *(const float4*)&Bs[kk][tx * 4];
            *(float4*)&b[4] = *(const float4*)&Bs[kk][64 + tx * 4];
#pragma unroll
            for (int i = 0; i < 8; ++i)
#pragma unroll
                for (int j = 0; j < 8; ++j)
                    acc[i][j] = fmaf(a[i], b[j], acc[i][j]);
        }
        __syncthreads();
    }

    // ---- epilogue ----
    int rows[8];
#pragma unroll
    for (int i = 0; i < 8; ++i)
        rows[i] = m0 + (i < 4 ? ty * 4 + i : 64 + ty * 4 + (i - 4));

#pragma unroll
    for (int i = 0; i < 8; ++i) {
#pragma unroll
        for (int jg = 0; jg < 2; ++jg) {
            const int cn = n0 + jg * 64 + tx * 4;
            if (cn >= N) continue;
            const long idx = (long)rows[i] * ldc + cn;
            float a0 = acc[i][jg * 4 + 0], a1 = acc[i][jg * 4 + 1];
            float a2 = acc[i][jg * 4 + 2], a3 = acc[i][jg * 4 + 3];
            if (EPI == 0) {
                *(float4*)&C[idx] = make_float4(a0, a1, a2, a3);
            } else if (EPI == 1) {
                float4 q = *(const float4*)&Qp[idx];
                const float ir = 1.0f / RHO_F;
                *(float4*)&C[idx] = make_float4((q.x - a0) * ir, (q.y - a1) * ir,
                                                (q.z - a2) * ir, (q.w - a3) * ir);
            } else { // EPI == 2
                float4 q = *(const float4*)&Qp[idx];
                float4 v = *(const float4*)&Vp[idx];
                float4 u = *(const float4*)&Up[idx];
                float4 vn, un;
                {
                    float x = q.x + v.x - a0; float z = fmaxf(x + u.x - THR_F, 0.f);
                    un.x = u.x + x - z; vn.x = is_last ? z : (2.f * z - u.x - x);
                }
                {
                    float x = q.y + v.y - a1; float z = fmaxf(x + u.y - THR_F, 0.f);
                    un.y = u.y + x - z; vn.y = is_last ? z : (2.f * z - u.y - x);
                }
                {
                    float x = q.z + v.z - a2; float z = fmaxf(x + u.z - THR_F, 0.f);
                    un.z = u.z + x - z; vn.z = is_last ? z : (2.f * z - u.z - x);
                }
                {
                    float x = q.w + v.w - a3; float z = fmaxf(x + u.w - THR_F, 0.f);
                    un.w = u.w + x - z; vn.w = is_last ? z : (2.f * z - u.w - x);
                }
                *(float4*)&C[idx]    = vn;
                *(float4*)&Uout[idx] = un;
            }
        }
    }
}

// ---------------------------------------------------------------------------
// Split-K reductions (deterministic, no atomics)
// ---------------------------------------------------------------------------
__global__ void reduce_sum(const float4* __restrict__ P, float4* __restrict__ out,
                           int n4, int S)
{
    int i = blockIdx.x * blockDim.x + threadIdx.x;
    if (i >= n4) return;
    float4 s = P[i];
    for (int k = 1; k < S; ++k) {
        float4 t = P[(long)k * n4 + i];
        s.x += t.x; s.y += t.y; s.z += t.z; s.w += t.w;
    }
    out[i] = s;
}

__global__ void reduce_G(const float* __restrict__ P, float* __restrict__ G, int S)
{
    int i = blockIdx.x * blockDim.x + threadIdx.x;
    if (i >= DM * DM) return;
    float s = 0.f;
    for (int k = 0; k < S; ++k) s += P[(long)k * DM * DM + i];
    if ((i / DM) == (i % DM)) s += RHO_F;
    G[i] = s;
}

__global__ void reduce_ns(const float4* __restrict__ P, const float4* __restrict__ Xc,
                          float4* __restrict__ Xn, int n4, int S)
{
    int i = blockIdx.x * blockDim.x + threadIdx.x;
    if (i >= n4) return;
    float4 s = P[i];
    for (int k = 1; k < S; ++k) {
        float4 t = P[(long)k * n4 + i];
        s.x += t.x; s.y += t.y; s.z += t.z; s.w += t.w;
    }
    float4 x = Xc[i];
    Xn[i] = make_float4(2.f * x.x - s.x, 2.f * x.y - s.y,
                        2.f * x.z - s.z, 2.f * x.w - s.w);
}

// ---------------------------------------------------------------------------
// ||G||_inf (== ||G||_1, symmetric); column sums for coalescing
// ---------------------------------------------------------------------------
__global__ void ninf_kernel(const float* __restrict__ G)
{
    __shared__ float sm[DM];
    const int i = threadIdx.x;
    float s = 0.f;
    for (int j = 0; j < DM; ++j) s += fabsf(G[(long)j * DM + i]);
    sm[i] = s;
    __syncthreads();
    for (int o = DM / 2; o > 0; o >>= 1) {
        if (i < o) sm[i] = fmaxf(sm[i], sm[i + o]);
        __syncthreads();
    }
    if (i == 0) g_ninf = sm[0];
}

__global__ void x0_kernel(float* __restrict__ X)
{
    int i = blockIdx.x * blockDim.x + threadIdx.x;
    if (i >= DM * DM) return;
    float c = 2.0f / (RHO_F + g_ninf);
    X[i] = ((i / DM) == (i % DM)) ? c : 0.0f;
}

// ---------------------------------------------------------------------------
// Row-normalize kernels (one block / row, 128 threads * float4)
// ---------------------------------------------------------------------------
__device__ __forceinline__ float block_sum128(float v, float* red)
{
    for (int o = 16; o > 0; o >>= 1) v += __shfl_xor_sync(0xffffffff, v, o);
    if ((threadIdx.x & 31) == 0) red[threadIdx.x >> 5] = v;
    __syncthreads();
    float tot = red[0] + red[1] + red[2] + red[3];
    __syncthreads();
    return tot;
}

// out = normalize(normalize(img) - mean)
__global__ void norm_center_kernel(const float* __restrict__ img,
                                   const float* __restrict__ mean,
                                   float* __restrict__ out)
{
    __shared__ float red[4];
    const int r = blockIdx.x, t = threadIdx.x;
    float4 v = ((const float4*)(img + (long)r * DM))[t];
    float ss = v.x * v.x + v.y * v.y + v.z * v.z + v.w * v.w;
    float inv = 1.0f / fmaxf(sqrtf(block_sum128(ss, red)), EPS_F);
    float4 mv = ((const float4*)mean)[t];
    float4 c = make_float4(v.x * inv - mv.x, v.y * inv - mv.y,
                           v.z * inv - mv.z, v.w * inv - mv.w);
    float ss2 = c.x * c.x + c.y * c.y + c.z * c.z + c.w * c.w;
    float inv2 = 1.0f / fmaxf(sqrtf(block_sum128(ss2, red)), EPS_F);
    ((float4*)(out + (long)r * DM))[t] =
        make_float4(c.x * inv2, c.y * inv2, c.z * inv2, c.w * inv2);
}

// out = normalize(row)
__global__ void norm_rows_kernel(const float* __restrict__ in, float* __restrict__ out)
{
    __shared__ float red[4];
    const int r = blockIdx.x, t = threadIdx.x;
    float4 v = ((const float4*)(in + (long)r * DM))[t];
    float ss = v.x * v.x + v.y * v.y + v.z * v.z + v.w * v.w;
    float inv = 1.0f / fmaxf(sqrtf(block_sum128(ss, red)), EPS_F);
    ((float4*)(out + (long)r * DM))[t] =
        make_float4(v.x * inv, v.y * inv, v.z * inv, v.w * inv);
}

// out = normalize(normalize(rec) + mean)
__global__ void final_norm_kernel(const float* __restrict__ rec,
                                  const float* __restrict__ mean,
                                  float* __restrict__ out)
{
    __shared__ float red[4];
    const int r = blockIdx.x, t = threadIdx.x;
    float4 v = ((const float4*)(rec + (long)r * DM))[t];
    float ss = v.x * v.x + v.y * v.y + v.z * v.z + v.w * v.w;
    float inv = 1.0f / fmaxf(sqrtf(block_sum128(ss, red)), EPS_F);
    float4 mv = ((const float4*)mean)[t];
    float4 c = make_float4(v.x * inv + mv.x, v.y * inv + mv.y,
                           v.z * inv + mv.z, v.w * inv + mv.w);
    float ss2 = c.x * c.x + c.y * c.y + c.z * c.z + c.w * c.w;
    float inv2 = 1.0f / fmaxf(sqrtf(block_sum128(ss2, red)), EPS_F);
    ((float4*)(out + (long)r * DM))[t] =
        make_float4(c.x * inv2, c.y * inv2, c.z * inv2, c.w * inv2);
}

// ---------------------------------------------------------------------------
// Host orchestration (graph-capturable: launches + memsets only)
// ---------------------------------------------------------------------------
extern "C" void kernel_launch(void* const* d_in, const int* in_sizes, int n_in,
                              void* d_out, int out_size)
{
    const float* dImg  = (const float*)d_in[0];
    const float* dTxt  = (const float*)d_in[1];
    const float* dMean = (const float*)d_in[2];
    const float* dDict = (const float*)d_in[3];
    float* outRecon = (float*)d_out;
    float* outTxt   = (float*)d_out + (long)BROWS * DM;

    float *Q, *V, *U, *E, *P, *W, *Y, *G, *XA, *XB, *T;
    cudaGetSymbolAddress((void**)&Q,  g_Q);
    cudaGetSymbolAddress((void**)&V,  g_V);
    cudaGetSymbolAddress((void**)&U,  g_U);
    cudaGetSymbolAddress((void**)&E,  g_E);
    cudaGetSymbolAddress((void**)&P,  g_P);
    cudaGetSymbolAddress((void**)&W,  g_W);
    cudaGetSymbolAddress((void**)&Y,  g_Y);
    cudaGetSymbolAddress((void**)&G,  g_G);
    cudaGetSymbolAddress((void**)&XA, g_XA);
    cudaGetSymbolAddress((void**)&XB, g_XB);
    cudaGetSymbolAddress((void**)&T,  g_T);

    const int NT = (CDICT + BN - 1) / BN;           // 79 tiles over N=10000
    const int KS = CDICT / KSPLIT;                  // 2000 per split slice

    // 1) centered = normalize(normalize(image) - mean); txt output
    norm_center_kernel<<<BROWS, 128>>>(dImg, dMean, Y);
    norm_rows_kernel<<<BROWS, 128>>>(dTxt, outTxt);

    // 2) Aty = Y @ D^T  -> Q   (NT gemm: M=1024, N=10000, K=512)
    gemm_kernel<false, true, 0><<<dim3(NT, 8, 1), 256>>>(
        Y, dDict, Q, BROWS, CDICT, DM, DM, DM, CDICT,
        nullptr, nullptr, nullptr, nullptr, 0);

    // 3) G = D^T D + rho I   (TN gemm, split-K)
    gemm_kernel<true, false, 0><<<dim3(4, 4, KSPLIT), 256>>>(
        dDict, dDict, P, DM, DM, KS, DM, DM, DM,
        nullptr, nullptr, nullptr, nullptr, 0);
    reduce_G<<<(DM * DM + 255) / 256, 256>>>(P, G, KSPLIT);

    // 4) Newton-Schulz inverse: X0 = (2/(rho+||G||inf)) I
    ninf_kernel<<<1, DM>>>(G);
    x0_kernel<<<(DM * DM + 255) / 256, 256>>>(XA);
    float* Xc = XA; float* Xn = XB;
    for (int t = 0; t < NS_ITERS; ++t) {
        gemm_kernel<false, false, 0><<<dim3(4, 4, 4), 256>>>(
            G, Xc, P, DM, DM, DM / 4, DM, DM, DM,
            nullptr, nullptr, nullptr, nullptr, 0);
        reduce_sum<<<(DM * DM / 4 + 255) / 256, 256>>>(
            (const float4*)P, (float4*)T, DM * DM / 4, 4);
        gemm_kernel<false, false, 0><<<dim3(4, 4, 4), 256>>>(
            Xc, T, P, DM, DM, DM / 4, DM, DM, DM,
            nullptr, nullptr, nullptr, nullptr, 0);
        reduce_ns<<<(DM * DM / 4 + 255) / 256, 256>>>(
            (const float4*)P, (const float4*)Xc, (float4*)Xn, DM * DM / 4, 4);
        float* tmp = Xc; Xc = Xn; Xn = tmp;
    }

    // 5) E = G^{-1} @ D^T   (NT gemm: M=512, N=10000, K=512)
    gemm_kernel<false, true, 0><<<dim3(NT, 4, 1), 256>>>(
        Xc, dDict, E, DM, CDICT, DM, DM, DM, CDICT,
        nullptr, nullptr, nullptr, nullptr, 0);

    // 6) q = (Aty - (Aty @ D) @ E) / rho   (in place on Q)
    gemm_kernel<false, false, 0><<<dim3(4, 8, KSPLIT), 256>>>(
        Q, dDict, P, BROWS, DM, KS, CDICT, DM, DM,
        nullptr, nullptr, nullptr, nullptr, 0);
    reduce_sum<<<(BROWS * DM / 4 + 255) / 256, 256>>>(
        (const float4*)P, (float4*)W, BROWS * DM / 4, KSPLIT);
    gemm_kernel<false, false, 1><<<dim3(NT, 8, 1), 256>>>(
        W, E, Q, BROWS, CDICT, DM, DM, CDICT, CDICT,
        Q, nullptr, nullptr, nullptr, 0);

    // 7) ADMM loop on (v, u); state z never materialized except last iter
    cudaMemsetAsync(V, 0, sizeof(float) * (size_t)BROWS * CDICT, 0);
    cudaMemsetAsync(U, 0, sizeof(float) * (size_t)BROWS * CDICT, 0);
    for (int it = 0; it < ADMM_ITERS; ++it) {
        gemm_kernel<false, false, 0><<<dim3(4, 8, KSPLIT), 256>>>(
            V, dDict, P, BROWS, DM, KS, CDICT, DM, DM,
            nullptr, nullptr, nullptr, nullptr, 0);
        reduce_sum<<<(BROWS * DM / 4 + 255) / 256, 256>>>(
            (const float4*)P, (float4*)W, BROWS * DM / 4, KSPLIT);
        gemm_kernel<false, false, 2><<<dim3(NT, 8, 1), 256>>>(
            W, E, V, BROWS, CDICT, DM, DM, CDICT, CDICT,
            Q, V, U, U, (it == ADMM_ITERS - 1) ? 1 : 0);
    }

    // 8) recon = normalize(normalize(z @ D) + mean)
    gemm_kernel<false, false, 0><<<dim3(4, 8, KSPLIT), 256>>>(
        V, dDict, P, BROWS, DM, KS, CDICT, DM, DM,
        nullptr, nullptr, nullptr, nullptr, 0);
    reduce_sum<<<(BROWS * DM / 4 + 255) / 256, 256>>>(
        (const float4*)P, (float4*)W, BROWS * DM / 4, KSPLIT);
    final_norm_kernel<<<BROWS, 128>>>(W, dMean, outRecon);
}

// round 2
// speedup vs baseline: 1.1879x; 1.1879x over previous
#include <cuda_runtime.h>
#include <math.h>
#include <stdint.h>

// ---------------------------------------------------------------------------
// Problem constants
// ---------------------------------------------------------------------------
#define BROWS 1024      // batch
#define CDICT 10000     // dictionary atoms
#define DM    512       // embedding dim
#define RHO_F 5.0f
#define THR_F 0.002f    // lam / rho
#define EPS_F 1e-12f
#define ADMM_ITERS 100
#define NS_ITERS 12
#define KSPLIT 5        // split-K slices for K=10000 GEMM (2000 per slice)
#define PADE 512        // tail padding (floats) so zfill-predicated OOB addrs stay in-bounds

// ---------------------------------------------------------------------------
// Scratch (static device globals -- no cudaMalloc allowed)
// ---------------------------------------------------------------------------
__device__ float g_Q  [(size_t)BROWS * CDICT + PADE];  // Aty, then q
__device__ float g_U  [(size_t)BROWS * CDICT + PADE];  // u
__device__ float g_Vhi[(size_t)BROWS * CDICT + PADE];  // tf32-hi of v
__device__ float g_Vlo[(size_t)BROWS * CDICT + PADE];  // tf32-lo of v
__device__ float g_Dhi[(size_t)CDICT * DM + PADE];
__device__ float g_Dlo[(size_t)CDICT * DM + PADE];
__device__ float g_E  [(size_t)DM * CDICT + PADE];     // E = G^{-1} D^T (fp32)
__device__ float g_Ehi[(size_t)DM * CDICT + PADE];
__device__ float g_Elo[(size_t)DM * CDICT + PADE];
__device__ float g_P  [(size_t)KSPLIT * BROWS * DM + PADE]; // split-K partials
__device__ float g_W  [(size_t)BROWS * DM + PADE];
__device__ float g_Whi[(size_t)BROWS * DM + PADE];
__device__ float g_Wlo[(size_t)BROWS * DM + PADE];
__device__ float g_Y  [(size_t)BROWS * DM + PADE];
__device__ float g_G [DM * DM];
__device__ float g_XA[DM * DM];
__device__ float g_XB[DM * DM];
__device__ float g_T [DM * DM];
__device__ float g_ninf;

// ---------------------------------------------------------------------------
// tf32 helpers
// ---------------------------------------------------------------------------
__device__ __forceinline__ void split_tf32(float v, float& h, float& l)
{
    unsigned hb; asm("cvt.rna.tf32.f32 %0, %1;" : "=r"(hb) : "f"(v));
    h = __uint_as_float(hb);
    float r = v - h;
    unsigned lb; asm("cvt.rna.tf32.f32 %0, %1;" : "=r"(lb) : "f"(r));
    l = __uint_as_float(lb);
}

__device__ __forceinline__ void mma8(float* c, const unsigned* a,
                                     unsigned b0, unsigned b1)
{
    asm volatile(
        "mma.sync.aligned.m16n8k8.row.col.f32.tf32.tf32.f32 "
        "{%0,%1,%2,%3}, {%4,%5,%6,%7}, {%8,%9}, {%0,%1,%2,%3};"
        : "+f"(c[0]), "+f"(c[1]), "+f"(c[2]), "+f"(c[3])
        : "r"(a[0]), "r"(a[1]), "r"(a[2]), "r"(a[3]), "r"(b0), "r"(b1));
}

__device__ __forceinline__ void cp16(uint32_t s, const void* g, bool p)
{
    int sz = p ? 16 : 0;
    asm volatile("cp.async.cg.shared.global [%0], [%1], 16, %2;"
                 :: "r"(s), "l"(g), "r"(sz) : "memory");
}

// ---------------------------------------------------------------------------
// tf32 MMA GEMM: C[M,N] = A[M,K] * B[K,N], A/B pre-split into (hi, lo).
// 3xTF32: acc = Ah*Bh + Ah*Bl + Al*Bh.   BM=BN=128, BK=16, 256 thr, 8 warps
// warp tile 32x64 (2 m16-tiles x 8 n8-tiles).  2-stage cp.async pipeline.
// blockIdx.z = split-K slice (EPI 0 writes partial at C + z*M*ldc).
// EPI 0: plain partial store
// EPI 2: ADMM fused: v=Vh+Vl; x=Q+v-acc; z=max(x+U-thr,0); U'=U+x-z;
//        vnew = is_last ? z : 2z-U-x; split vnew -> Vh,Vl.
// ---------------------------------------------------------------------------
#define MMA_STG   37888            // bytes per pipeline stage
#define MMA_SMEM  (2 * MMA_STG)    // 2 stages
// stage layout (floats): Ah[128][20] @0, Al @2560, Bh[16][136] @5120, Bl @7296

template<int EPI>
__global__ void __launch_bounds__(256, 2)
mma_gemm(const float* __restrict__ Ah, const float* __restrict__ Al,
         const float* __restrict__ Bh, const float* __restrict__ Bl,
         float* __restrict__ C, int M, int N, int Kslice,
         int lda, int ldb, int ldc,
         const float* __restrict__ Qp, float* __restrict__ Up,
         float* __restrict__ Vh, float* __restrict__ Vl, int is_last)
{
    extern __shared__ char sm_dyn[];
    const int tid  = threadIdx.x;
    const int lane = tid & 31, wid = tid >> 5;
    const int wm = (wid & 3) * 32;       // warp m offset
    const int wn = (wid >> 2) * 64;      // warp n offset
    const int gq = lane >> 2, tq = lane & 3;
    const int m0 = blockIdx.y * 128, n0 = blockIdx.x * 128;
    const long k0 = (long)blockIdx.z * Kslice;
    const int nk = Kslice >> 4;

    float c[2][8][4];
#pragma unroll
    for (int i = 0; i < 2; ++i)
#pragma unroll
        for (int j = 0; j < 8; ++j)
#pragma unroll
            for (int q = 0; q < 4; ++q) c[i][j][q] = 0.0f;

    // ---- tile loader (cp.async) ----
    auto load_tile = [&](int kt, int buf) {
        char* base = sm_dyn + buf * MMA_STG;
        const int kbase = kt * 16;
#pragma unroll
        for (int cc = 0; cc < 2; ++cc) {             // A: 128x16, 4 chunks/row
            int ch  = tid * 2 + cc;
            int row = ch >> 2, kc = (ch & 3) * 4;
            uint32_t so = (uint32_t)__cvta_generic_to_shared(
                base + (row * 20 + kc) * 4);
            const long go = (long)(m0 + row) * lda + k0 + kbase + kc;
            cp16(so,         Ah + go, true);
            cp16(so + 10240, Al + go, true);
        }
#pragma unroll
        for (int cc = 0; cc < 2; ++cc) {             // B: 16x128, 32 chunks/row
            int ch  = tid * 2 + cc;
            int row = ch >> 5, nc = (ch & 31) * 4;
            bool p = (n0 + nc) < N;
            uint32_t so = (uint32_t)__cvta_generic_to_shared(
                base + 20480 + (row * 136 + nc) * 4);
            const long go = (long)(k0 + kbase + row) * ldb + n0 + nc;
            cp16(so,        Bh + go, p);
            cp16(so + 8704, Bl + go, p);
        }
    };

    load_tile(0, 0);
    asm volatile("cp.async.commit_group;" ::: "memory");

    for (int kt = 0; kt < nk; ++kt) {
        asm volatile("cp.async.wait_group 0;" ::: "memory");
        __syncthreads();
        if (kt + 1 < nk) load_tile(kt + 1, (kt + 1) & 1);
        asm volatile("cp.async.commit_group;" ::: "memory");

        const float* AHb = (const float*)(sm_dyn + (kt & 1) * MMA_STG);
        const float* ALb = AHb + 2560;
        const float* BHb = AHb + 5120;
        const float* BLb = AHb + 7296;

#pragma unroll
        for (int ks = 0; ks < 2; ++ks) {
            unsigned ah[2][4], al[2][4];
#pragma unroll
            for (int i = 0; i < 2; ++i) {
                const float* p = AHb + (wm + i * 16 + gq) * 20 + ks * 8 + tq;
                ah[i][0] = __float_as_uint(p[0]);
                ah[i][1] = __float_as_uint(p[8 * 20]);
                ah[i][2] = __float_as_uint(p[4]);
                ah[i][3] = __float_as_uint(p[8 * 20 + 4]);
                const float* q = ALb + (wm + i * 16 + gq) * 20 + ks * 8 + tq;
                al[i][0] = __float_as_uint(q[0]);
                al[i][1] = __float_as_uint(q[8 * 20]);
                al[i][2] = __float_as_uint(q[4]);
                al[i][3] = __float_as_uint(q[8 * 20 + 4]);
            }
#pragma unroll
            for (int j = 0; j < 8; ++j) {
                const int nn = wn + j * 8 + gq;
                const float* bp = BHb + (ks * 8 + tq) * 136 + nn;
                unsigned bh0 = __float_as_uint(bp[0]);
                unsigned bh1 = __float_as_uint(bp[4 * 136]);
                const float* bq = BLb + (ks * 8 + tq) * 136 + nn;
                unsigned bl0 = __float_as_uint(bq[0]);
                unsigned bl1 = __float_as_uint(bq[4 * 136]);
#pragma unroll
                for (int i = 0; i < 2; ++i) {
                    mma8(c[i][j], ah[i], bh0, bh1);
                    mma8(c[i][j], ah[i], bl0, bl1);
                    mma8(c[i][j], al[i], bh0, bh1);
                }
            }
        }
    }

    // ---- epilogue ----
#pragma unroll
    for (int i = 0; i < 2; ++i) {
        const int r0 = m0 + wm + i * 16 + gq;
#pragma unroll
        for (int j = 0; j < 8; ++j) {
            const int ccn = n0 + wn + j * 8 + 2 * tq;
            if (ccn >= N) continue;
            if (EPI == 0) {
                float* Cz = C + (long)blockIdx.z * (long)M * ldc;
                *(float2*)&Cz[(long)r0 * ldc + ccn] =
                    make_float2(c[i][j][0], c[i][j][1]);
                *(float2*)&Cz[(long)(r0 + 8) * ldc + ccn] =
                    make_float2(c[i][j][2], c[i][j][3]);
            } else {
#pragma unroll
                for (int rr = 0; rr < 2; ++rr) {
                    const long idx = (long)(r0 + rr * 8) * ldc + ccn;
                    float a0 = c[i][j][rr * 2 + 0], a1 = c[i][j][rr * 2 + 1];
                    float2 qv = *(const float2*)&Qp[idx];
                    float2 uv = *(const float2*)&Up[idx];
                    float2 vh = *(const float2*)&Vh[idx];
                    float2 vl = *(const float2*)&Vl[idx];
                    float2 un, nh, nl;
                    {
                        float v = vh.x + vl.x;
                        float x = qv.x + v - a0;
                        float z = fmaxf(x + uv.x - THR_F, 0.f);
                        un.x = uv.x + x - z;
                        float vn = is_last ? z : (2.f * z - uv.x - x);
                        split_tf32(vn, nh.x, nl.x);
                    }
                    {
                        float v = vh.y + vl.y;
                        float x = qv.y + v - a1;
                        float z = fmaxf(x + uv.y - THR_F, 0.f);
                        un.y = uv.y + x - z;
                        float vn = is_last ? z : (2.f * z - uv.y - x);
                        split_tf32(vn, nh.y, nl.y);
                    }
                    *(float2*)&Up[idx] = un;
                    *(float2*)&Vh[idx] = nh;
                    *(float2*)&Vl[idx] = nl;
                }
            }
        }
    }
}

// ---------------------------------------------------------------------------
// SIMT tiled SGEMM (setup path only -- full fp32 accuracy)
// ---------------------------------------------------------------------------
#define BM 128
#define BN 128
#define BKK 16

template<bool TA, bool TB, int EPI>
__global__ void __launch_bounds__(256, 2)
gemm_kernel(const float* __restrict__ A, const float* __restrict__ B,
            float* __restrict__ C,
            int M, int N, int Kslice, int lda, int ldb, int ldc,
            const float* __restrict__ Qp)
{
    __shared__ float As[BKK][BM + 4];
    __shared__ float Bs[BKK][BN + 4];

    const int tid = threadIdx.x;
    const int tx  = tid & 15;
    const int ty  = tid >> 4;
    const int m0  = blockIdx.y * BM;
    const int n0  = blockIdx.x * BN;

    const long k0 = (long)blockIdx.z * Kslice;
    if (TA) A += k0 * lda; else A += k0;
    if (TB) B += k0;       else B += k0 * ldb;
    if (EPI == 0) C += (long)blockIdx.z * (long)M * ldc;

    float acc[8][8];
#pragma unroll
    for (int i = 0; i < 8; ++i)
#pragma unroll
        for (int j = 0; j < 8; ++j) acc[i][j] = 0.0f;

    const int nk = Kslice / BKK;
#pragma unroll 1
    for (int kt = 0; kt < nk; ++kt) {
        const int kbase = kt * BKK;
        if (!TA) {
#pragma unroll
            for (int p = 0; p < 2; ++p) {
                const int row = p * 64 + (tid >> 2);
                const int c4  = (tid & 3) * 4;
                float4 v = *(const float4*)&A[(long)(m0 + row) * lda + kbase + c4];
                As[c4 + 0][row] = v.x; As[c4 + 1][row] = v.y;
                As[c4 + 2][row] = v.z; As[c4 + 3][row] = v.w;
            }
        } else {
#pragma unroll
            for (int p = 0; p < 2; ++p) {
                const int kr = p * 8 + (tid >> 5);
                const int m4 = (tid & 31) * 4;
                float4 v = *(const float4*)&A[(long)(kbase + kr) * lda + m0 + m4];
                *(float4*)&As[kr][m4] = v;
            }
        }
        if (!TB) {
#pragma unroll
            for (int p = 0; p < 2; ++p) {
                const int kr  = p * 8 + (tid >> 5);
                const int nn4 = (tid & 31) * 4;
                const int gn  = n0 + nn4;
                float4 v = make_float4(0.f, 0.f, 0.f, 0.f);
                if (gn < N) v = *(const float4*)&B[(long)(kbase + kr) * ldb + gn];
                *(float4*)&Bs[kr][nn4] = v;
            }
        } else {
#pragma unroll
            for (int p = 0; p < 2; ++p) {
                const int nrow = p * 64 + (tid >> 2);
                const int c4   = (tid & 3) * 4;
                const int gn   = n0 + nrow;
                float4 v = make_float4(0.f, 0.f, 0.f, 0.f);
                if (gn < N) v = *(const float4*)&B[(long)gn * ldb + kbase + c4];
                Bs[c4 + 0][nrow] = v.x; Bs[c4 + 1][nrow] = v.y;
                Bs[c4 + 2][nrow] = v.z; Bs[c4 + 3][nrow] = v.w;
            }
        }
        __syncthreads();
#pragma unroll
        for (int kk = 0; kk < BKK; ++kk) {
            float a[8], b[8];
            *(float4*)&a[0] = *(const float4*)&As[kk][ty * 4];
            *(float4*)&a[4] = *(const float4*)&As[kk][64 + ty * 4];
            *(float4*)&b[0] = *(const float4*)&Bs[kk][tx * 4];
            *(float4*)&b[4] = *(const float4*)&Bs[kk][64 + tx * 4];
#pragma unroll
            for (int i = 0; i < 8; ++i)
#pragma unroll
                for (int j = 0; j < 8; ++j)
                    acc[i][j] = fmaf(a[i], b[j], acc[i][j]);
        }
        __syncthreads();
    }

    int rows[8];
#pragma unroll
    for (int i = 0; i < 8; ++i)
        rows[i] = m0 + (i < 4 ? ty * 4 + i : 64 + ty * 4 + (i - 4));

#pragma unroll
    for (int i = 0; i < 8; ++i) {
#pragma unroll
        for (int jg = 0; jg < 2; ++jg) {
            const int cn = n0 + jg * 64 + tx * 4;
            if (cn >= N) continue;
            const long idx = (long)rows[i] * ldc + cn;
            float a0 = acc[i][jg * 4 + 0], a1 = acc[i][jg * 4 + 1];
            float a2 = acc[i][jg * 4 + 2], a3 = acc[i][jg * 4 + 3];
            if (EPI == 0) {
                *(float4*)&C[idx] = make_float4(a0, a1, a2, a3);
            } else { // EPI 1: q = (Aty - acc) / rho
                float4 q = *(const float4*)&Qp[idx];
                const float ir = 1.0f / RHO_F;
                *(float4*)&C[idx] = make_float4((q.x - a0) * ir, (q.y - a1) * ir,
                                                (q.z - a2) * ir, (q.w - a3) * ir);
            }
        }
    }
}

// ---------------------------------------------------------------------------
// Reductions / splits
// ---------------------------------------------------------------------------
__global__ void reduce_sum(const float4* __restrict__ P, float4* __restrict__ out,
                           int n4, int S)
{
    int i = blockIdx.x * blockDim.x + threadIdx.x;
    if (i >= n4) return;
    float4 s = P[i];
    for (int k = 1; k < S; ++k) {
        float4 t = P[(long)k * n4 + i];
        s.x += t.x; s.y += t.y; s.z += t.z; s.w += t.w;
    }
    out[i] = s;
}

__global__ void reduce_split_k(const float4* __restrict__ P,
                               float4* __restrict__ Wh, float4* __restrict__ Wl,
                               int n4, int S)
{
    int i = blockIdx.x * blockDim.x + threadIdx.x;
    if (i >= n4) return;
    float4 s = P[i];
    for (int k = 1; k < S; ++k) {
        float4 t = P[(long)k * n4 + i];
        s.x += t.x; s.y += t.y; s.z += t.z; s.w += t.w;
    }
    float4 h, l;
    split_tf32(s.x, h.x, l.x); split_tf32(s.y, h.y, l.y);
    split_tf32(s.z, h.z, l.z); split_tf32(s.w, h.w, l.w);
    Wh[i] = h; Wl[i] = l;
}

__global__ void split_mat(const float4* __restrict__ src, float4* __restrict__ hi,
                          float4* __restrict__ lo, int n4)
{
    int i = blockIdx.x * blockDim.x + threadIdx.x;
    if (i >= n4) return;
    float4 v = src[i];
    float4 h, l;
    split_tf32(v.x, h.x, l.x); split_tf32(v.y, h.y, l.y);
    split_tf32(v.z, h.z, l.z); split_tf32(v.w, h.w, l.w);
    hi[i] = h; lo[i] = l;
}

__global__ void reduce_G(const float* __restrict__ P, float* __restrict__ G, int S)
{
    int i = blockIdx.x * blockDim.x + threadIdx.x;
    if (i >= DM * DM) return;
    float s = 0.f;
    for (int k = 0; k < S; ++k) s += P[(long)k * DM * DM + i];
    if ((i / DM) == (i % DM)) s += RHO_F;
    G[i] = s;
}

__global__ void reduce_ns(const float4* __restrict__ P, const float4* __restrict__ Xc,
                          float4* __restrict__ Xn, int n4, int S)
{
    int i = blockIdx.x * blockDim.x + threadIdx.x;
    if (i >= n4) return;
    float4 s = P[i];
    for (int k = 1; k < S; ++k) {
        float4 t = P[(long)k * n4 + i];
        s.x += t.x; s.y += t.y; s.z += t.z; s.w += t.w;
    }
    float4 x = Xc[i];
    Xn[i] = make_float4(2.f * x.x - s.x, 2.f * x.y - s.y,
                        2.f * x.z - s.z, 2.f * x.w - s.w);
}

__global__ void ninf_kernel(const float* __restrict__ G)
{
    __shared__ float sm[DM];
    const int i = threadIdx.x;
    float s = 0.f;
    for (int j = 0; j < DM; ++j) s += fabsf(G[(long)j * DM + i]);
    sm[i] = s;
    __syncthreads();
    for (int o = DM / 2; o > 0; o >>= 1) {
        if (i < o) sm[i] = fmaxf(sm[i], sm[i + o]);
        __syncthreads();
    }
    if (i == 0) g_ninf = sm[0];
}

__global__ void x0_kernel(float* __restrict__ X)
{
    int i = blockIdx.x * blockDim.x + threadIdx.x;
    if (i >= DM * DM) return;
    float c = 2.0f / (RHO_F + g_ninf);
    X[i] = ((i / DM) == (i % DM)) ? c : 0.0f;
}

// ---------------------------------------------------------------------------
// Row-normalize kernels
// ---------------------------------------------------------------------------
__device__ __forceinline__ float block_sum128(float v, float* red)
{
    for (int o = 16; o > 0; o >>= 1) v += __shfl_xor_sync(0xffffffff, v, o);
    if ((threadIdx.x & 31) == 0) red[threadIdx.x >> 5] = v;
    __syncthreads();
    float tot = red[0] + red[1] + red[2] + red[3];
    __syncthreads();
    return tot;
}

__global__ void norm_center_kernel(const float* __restrict__ img,
                                   const float* __restrict__ mean,
                                   float* __restrict__ out)
{
    __shared__ float red[4];
    const int r = blockIdx.x, t = threadIdx.x;
    float4 v = ((const float4*)(img + (long)r * DM))[t];
    float ss = v.x * v.x + v.y * v.y + v.z * v.z + v.w * v.w;
    float inv = 1.0f / fmaxf(sqrtf(block_sum128(ss, red)), EPS_F);
    float4 mv = ((const float4*)mean)[t];
    float4 c = make_float4(v.x * inv - mv.x, v.y * inv - mv.y,
                           v.z * inv - mv.z, v.w * inv - mv.w);
    float ss2 = c.x * c.x + c.y * c.y + c.z * c.z + c.w * c.w;
    float inv2 = 1.0f / fmaxf(sqrtf(block_sum128(ss2, red)), EPS_F);
    ((float4*)(out + (long)r * DM))[t] =
        make_float4(c.x * inv2, c.y * inv2, c.z * inv2, c.w * inv2);
}

__global__ void norm_rows_kernel(const float* __restrict__ in, float* __restrict__ out)
{
    __shared__ float red[4];
    const int r = blockIdx.x, t = threadIdx.x;
    float4 v = ((const float4*)(in + (long)r * DM))[t];
    float ss = v.x * v.x + v.y * v.y + v.z * v.z + v.w * v.w;
    float inv = 1.0f / fmaxf(sqrtf(block_sum128(ss, red)), EPS_F);
    ((float4*)(out + (long)r * DM))[t] =
        make_float4(v.x * inv, v.y * inv, v.z * inv, v.w * inv);
}

__global__ void final_norm_kernel(const float* __restrict__ rec,
                                  const float* __restrict__ mean,
                                  float* __restrict__ out)
{
    __shared__ float red[4];
    const int r = blockIdx.x, t = threadIdx.x;
    float4 v = ((const float4*)(rec + (long)r * DM))[t];
    float ss = v.x * v.x + v.y * v.y + v.z * v.z + v.w * v.w;
    float inv = 1.0f / fmaxf(sqrtf(block_sum128(ss, red)), EPS_F);
    float4 mv = ((const float4*)mean)[t];
    float4 c = make_float4(v.x * inv + mv.x, v.y * inv + mv.y,
                           v.z * inv + mv.z, v.w * inv + mv.w);
    float ss2 = c.x * c.x + c.y * c.y + c.z * c.z + c.w * c.w;
    float inv2 = 1.0f / fmaxf(sqrtf(block_sum128(ss2, red)), EPS_F);
    ((float4*)(out + (long)r * DM))[t] =
        make_float4(c.x * inv2, c.y * inv2, c.z * inv2, c.w * inv2);
}

// ---------------------------------------------------------------------------
// Host orchestration
// ---------------------------------------------------------------------------
extern "C" void kernel_launch(void* const* d_in, const int* in_sizes, int n_in,
                              void* d_out, int out_size)
{
    const float* dImg  = (const float*)d_in[0];
    const float* dTxt  = (const float*)d_in[1];
    const float* dMean = (const float*)d_in[2];
    const float* dDict = (const float*)d_in[3];
    float* outRecon = (float*)d_out;
    float* outTxt   = (float*)d_out + (long)BROWS * DM;

    float *Q, *U, *Vhi, *Vlo, *Dhi, *Dlo, *E, *Ehi, *Elo, *P, *W, *Whi, *Wlo,
          *Y, *G, *XA, *XB, *T;
    cudaGetSymbolAddress((void**)&Q,   g_Q);
    cudaGetSymbolAddress((void**)&U,   g_U);
    cudaGetSymbolAddress((void**)&Vhi, g_Vhi);
    cudaGetSymbolAddress((void**)&Vlo, g_Vlo);
    cudaGetSymbolAddress((void**)&Dhi, g_Dhi);
    cudaGetSymbolAddress((void**)&Dlo, g_Dlo);
    cudaGetSymbolAddress((void**)&E,   g_E);
    cudaGetSymbolAddress((void**)&Ehi, g_Ehi);
    cudaGetSymbolAddress((void**)&Elo, g_Elo);
    cudaGetSymbolAddress((void**)&P,   g_P);
    cudaGetSymbolAddress((void**)&W,   g_W);
    cudaGetSymbolAddress((void**)&Whi, g_Whi);
    cudaGetSymbolAddress((void**)&Wlo, g_Wlo);
    cudaGetSymbolAddress((void**)&Y,   g_Y);
    cudaGetSymbolAddress((void**)&G,   g_G);
    cudaGetSymbolAddress((void**)&XA,  g_XA);
    cudaGetSymbolAddress((void**)&XB,  g_XB);
    cudaGetSymbolAddress((void**)&T,   g_T);

    cudaFuncSetAttribute(mma_gemm<0>, cudaFuncAttributeMaxDynamicSharedMemorySize,
                         MMA_SMEM);
    cudaFuncSetAttribute(mma_gemm<2>, cudaFuncAttributeMaxDynamicSharedMemorySize,
                         MMA_SMEM);

    const int NT = (CDICT + BN - 1) / BN;   // 79
    const int KS = CDICT / KSPLIT;          // 2000

    // 1) centered inputs + text output
    norm_center_kernel<<<BROWS, 128>>>(dImg, dMean, Y);
    norm_rows_kernel<<<BROWS, 128>>>(dTxt, outTxt);

    // 2) Aty = Y @ D^T  -> Q
    gemm_kernel<false, true, 0><<<dim3(NT, 8, 1), 256>>>(
        Y, dDict, Q, BROWS, CDICT, DM, DM, DM, CDICT, nullptr);

    // 3) G = D^T D + rho I
    gemm_kernel<true, false, 0><<<dim3(4, 4, KSPLIT), 256>>>(
        dDict, dDict, P, DM, DM, KS, DM, DM, DM, nullptr);
    reduce_G<<<(DM * DM + 255) / 256, 256>>>(P, G, KSPLIT);

    // 4) Newton-Schulz inverse
    ninf_kernel<<<1, DM>>>(G);
    x0_kernel<<<(DM * DM + 255) / 256, 256>>>(XA);
    float* Xc = XA; float* Xn = XB;
    for (int t = 0; t < NS_ITERS; ++t) {
        gemm_kernel<false, false, 0><<<dim3(4, 4, 4), 256>>>(
            G, Xc, P, DM, DM, DM / 4, DM, DM, DM, nullptr);
        reduce_sum<<<(DM * DM / 4 + 255) / 256, 256>>>(
            (const float4*)P, (float4*)T, DM * DM / 4, 4);
        gemm_kernel<false, false, 0><<<dim3(4, 4, 4), 256>>>(
            Xc, T, P, DM, DM, DM / 4, DM, DM, DM, nullptr);
        reduce_ns<<<(DM * DM / 4 + 255) / 256, 256>>>(
            (const float4*)P, (const float4*)Xc, (float4*)Xn, DM * DM / 4, 4);
        float* tmp = Xc; Xc = Xn; Xn = tmp;
    }

    // 5) E = G^{-1} @ D^T
    gemm_kernel<false, true, 0><<<dim3(NT, 4, 1), 256>>>(
        Xc, dDict, E, DM, CDICT, DM, DM, DM, CDICT, nullptr);

    // splits for tf32 path
    split_mat<<<((CDICT * DM / 4) + 255) / 256, 256>>>(
        (const float4*)dDict, (float4*)Dhi, (float4*)Dlo, CDICT * DM / 4);
    split_mat<<<((DM * CDICT / 4) + 255) / 256, 256>>>(
        (const float4*)E, (float4*)Ehi, (float4*)Elo, DM * CDICT / 4);

    // 6) q = (Aty - (Aty @ D) @ E) / rho   (fp32 SIMT, in place on Q)
    gemm_kernel<false, false, 0><<<dim3(4, 8, KSPLIT), 256>>>(
        Q, dDict, P, BROWS, DM, KS, CDICT, DM, DM, nullptr);
    reduce_sum<<<(BROWS * DM / 4 + 255) / 256, 256>>>(
        (const float4*)P, (float4*)W, BROWS * DM / 4, KSPLIT);
    gemm_kernel<false, false, 1><<<dim3(NT, 8, 1), 256>>>(
        W, E, Q, BROWS, CDICT, DM, DM, CDICT, CDICT, Q);

    // 7) ADMM loop (tf32 3x-split tensor-core path)
    cudaMemsetAsync(Vhi, 0, sizeof(float) * (size_t)BROWS * CDICT, 0);
    cudaMemsetAsync(Vlo, 0, sizeof(float) * (size_t)BROWS * CDICT, 0);
    cudaMemsetAsync(U,   0, sizeof(float) * (size_t)BROWS * CDICT, 0);
    for (int it = 0; it < ADMM_ITERS; ++it) {
        mma_gemm<0><<<dim3(4, 8, KSPLIT), 256, MMA_SMEM>>>(
            Vhi, Vlo, Dhi, Dlo, P, BROWS, DM, KS, CDICT, DM, DM,
            nullptr, nullptr, nullptr, nullptr, 0);
        reduce_split_k<<<(BROWS * DM / 4 + 255) / 256, 256>>>(
            (const float4*)P, (float4*)Whi, (float4*)Wlo, BROWS * DM / 4, KSPLIT);
        mma_gemm<2><<<dim3(NT, 8, 1), 256, MMA_SMEM>>>(
            Whi, Wlo, Ehi, Elo, nullptr, BROWS, CDICT, DM, DM, CDICT, CDICT,
            Q, U, Vhi, Vlo, (it == ADMM_ITERS - 1) ? 1 : 0);
    }

    // 8) recon = normalize(normalize(z @ D) + mean)  (z lives split in Vhi/Vlo)
    mma_gemm<0><<<dim3(4, 8, KSPLIT), 256, MMA_SMEM>>>(
        Vhi, Vlo, Dhi, Dlo, P, BROWS, DM, KS, CDICT, DM, DM,
        nullptr, nullptr, nullptr, nullptr, 0);
    reduce_sum<<<(BROWS * DM / 4 + 255) / 256, 256>>>(
        (const float4*)P, (float4*)W, BROWS * DM / 4, KSPLIT);
    final_norm_kernel<<<BROWS, 128>>>(W, dMean, outRecon);
}

// round 3
// speedup vs baseline: 2.1797x; 1.8349x over previous
#include <cuda_runtime.h>
#include <cuda_bf16.h>
#include <math.h>
#include <stdint.h>

// ---------------------------------------------------------------------------
// Problem constants
// ---------------------------------------------------------------------------
#define BROWS 1024      // batch
#define CDICT 10000     // dictionary atoms
#define CPAD  10240     // padded dict dim: 5 * 2048, divisible by 32 and 128
#define DM    512       // embedding dim
#define RHO_F 5.0f
#define THR_F 0.002f    // lam / rho
#define EPS_F 1e-12f
#define ADMM_ITERS 100
#define NS_ITERS 12
#define KSPLIT 5        // split-K slices for the K=CPAD GEMM (2048 each)

// ---------------------------------------------------------------------------
// Scratch (static device globals -- no cudaMalloc allowed)
// ---------------------------------------------------------------------------
__device__ float          g_Q [(size_t)BROWS * CPAD];   // Aty, then q  (ld=CPAD)
__device__ float          g_U [(size_t)BROWS * CPAD];   // u            (ld=CPAD)
__device__ __nv_bfloat16  g_Vh[(size_t)BROWS * CPAD];   // bf16-hi of v
__device__ __nv_bfloat16  g_Vl[(size_t)BROWS * CPAD];   // bf16-lo of v
__device__ __nv_bfloat16  g_Dh[(size_t)CPAD * DM];      // dict hi [CPAD x 512]
__device__ __nv_bfloat16  g_Dl[(size_t)CPAD * DM];
__device__ float          g_E [(size_t)DM * CPAD];      // E = G^{-1} D^T (fp32, ld=CPAD)
__device__ __nv_bfloat16  g_Eh[(size_t)DM * CPAD];
__device__ __nv_bfloat16  g_El[(size_t)DM * CPAD];
__device__ float          g_P [(size_t)KSPLIT * BROWS * DM]; // split-K partials
__device__ float          g_W [(size_t)BROWS * DM];
__device__ __nv_bfloat16  g_Wh[(size_t)BROWS * DM];
__device__ __nv_bfloat16  g_Wl[(size_t)BROWS * DM];
__device__ float          g_Y [(size_t)BROWS * DM];
__device__ float g_G [DM * DM];
__device__ float g_XA[DM * DM];
__device__ float g_XB[DM * DM];
__device__ float g_T [DM * DM];
__device__ float g_ninf;

// ---------------------------------------------------------------------------
// helpers
// ---------------------------------------------------------------------------
__device__ __forceinline__ void split_bf16(float v, __nv_bfloat16& h, __nv_bfloat16& l)
{
    h = __float2bfloat16_rn(v);
    l = __float2bfloat16_rn(v - __bfloat162float(h));
}

__device__ __forceinline__ void mma16(float* c, const unsigned* a,
                                      unsigned b0, unsigned b1)
{
    asm volatile(
        "mma.sync.aligned.m16n8k16.row.col.f32.bf16.bf16.f32 "
        "{%0,%1,%2,%3}, {%4,%5,%6,%7}, {%8,%9}, {%0,%1,%2,%3};"
        : "+f"(c[0]), "+f"(c[1]), "+f"(c[2]), "+f"(c[3])
        : "r"(a[0]), "r"(a[1]), "r"(a[2]), "r"(a[3]), "r"(b0), "r"(b1));
}

__device__ __forceinline__ void ldsm4(unsigned* r, uint32_t a)
{
    asm volatile("ldmatrix.sync.aligned.m8n8.x4.shared.b16 {%0,%1,%2,%3}, [%4];"
                 : "=r"(r[0]), "=r"(r[1]), "=r"(r[2]), "=r"(r[3]) : "r"(a));
}

__device__ __forceinline__ void ldsm4t(unsigned* r, uint32_t a)
{
    asm volatile("ldmatrix.sync.aligned.m8n8.x4.trans.shared.b16 {%0,%1,%2,%3}, [%4];"
                 : "=r"(r[0]), "=r"(r[1]), "=r"(r[2]), "=r"(r[3]) : "r"(a));
}

__device__ __forceinline__ void cp16(uint32_t s, const void* g)
{
    asm volatile("cp.async.cg.shared.global [%0], [%1], 16;"
                 :: "r"(s), "l"(g) : "memory");
}

// ---------------------------------------------------------------------------
// bf16x3 MMA GEMM: C[M,N] = A[M,K] * B[K,N]; A,B pre-split (hi, lo) bf16.
// acc = Ah*Bh + Ah*Bl + Al*Bh  (fp32 accumulate).
// BM=BN=128, BK=32, 256 thr, 8 warps (warp tile 32x64), 2-stage cp.async.
// ldmatrix for all fragments (conflict-free strides 40 / 136 bf16).
// blockIdx.z = split-K slice; EPI 0 writes partial at C + z*M*ldc.
// EPI 2: fused ADMM: v=Vh+Vl; x=Q+v-acc; z=max(x+U-thr,0); U'=U+x-z;
//        vnew = is_last ? z : 2z-U-x; split vnew -> Vh,Vl (bf16).
// Stage layout (bytes): Ah[128][40]@0 (10240), Al@10240, Bh[32][136]@20480
// (8704), Bl@29184.  Stage = 37888 B, 2 stages = 75776 B dynamic smem.
// ---------------------------------------------------------------------------
#define BSTG  37888
#define BSMEM (2 * BSTG)

template<int EPI>
__global__ void __launch_bounds__(256, 2)
bmma_gemm(const __nv_bfloat16* __restrict__ Ah, const __nv_bfloat16* __restrict__ Al,
          const __nv_bfloat16* __restrict__ Bh, const __nv_bfloat16* __restrict__ Bl,
          float* __restrict__ C, int M, int N, int Kslice,
          int lda, int ldb, int ldc,
          const float* __restrict__ Qp, float* __restrict__ Up,
          __nv_bfloat16* __restrict__ Vh, __nv_bfloat16* __restrict__ Vl,
          int is_last)
{
    extern __shared__ char smd[];
    const int tid  = threadIdx.x;
    const int lane = tid & 31, wid = tid >> 5;
    const int wm = (wid & 3) * 32;
    const int wn = (wid >> 2) * 64;
    const int m0 = blockIdx.y * 128, n0 = blockIdx.x * 128;
    const long k0 = (long)blockIdx.z * Kslice;
    const int nk = Kslice >> 5;

    // ldmatrix per-lane addressing
    const int aRow = wm + ((lane >> 3) & 1) * 8 + (lane & 7);
    const int aKof = (lane >> 4) * 8;
    const int bRow = ((lane >> 3) & 1) * 8 + (lane & 7);
    const int bNof = (lane >> 4) * 8;

    float c[2][8][4];
#pragma unroll
    for (int i = 0; i < 2; ++i)
#pragma unroll
        for (int j = 0; j < 8; ++j)
#pragma unroll
            for (int q = 0; q < 4; ++q) c[i][j][q] = 0.0f;

    auto load_tile = [&](int kt, int buf) {
        char* base = smd + buf * BSTG;
        const int kb = kt * 32;
#pragma unroll
        for (int cc = 0; cc < 2; ++cc) {        // A: 128 rows x 4 chunks (8 bf16)
            int ch  = tid * 2 + cc;
            int row = ch >> 2, kc = (ch & 3) * 8;
            uint32_t so = (uint32_t)__cvta_generic_to_shared(
                base + (row * 40 + kc) * 2);
            const long go = (long)(m0 + row) * lda + k0 + kb + kc;
            cp16(so,         Ah + go);
            cp16(so + 10240, Al + go);
        }
#pragma unroll
        for (int cc = 0; cc < 2; ++cc) {        // B: 32 rows x 16 chunks
            int ch  = tid * 2 + cc;
            int row = ch >> 4, nc = (ch & 15) * 8;
            uint32_t so = (uint32_t)__cvta_generic_to_shared(
                base + 20480 + (row * 136 + nc) * 2);
            const long go = (long)(k0 + kb + row) * ldb + n0 + nc;
            cp16(so,        Bh + go);
            cp16(so + 8704, Bl + go);
        }
    };

    load_tile(0, 0);
    asm volatile("cp.async.commit_group;" ::: "memory");

    for (int kt = 0; kt < nk; ++kt) {
        asm volatile("cp.async.wait_group 0;" ::: "memory");
        __syncthreads();
        if (kt + 1 < nk) load_tile(kt + 1, (kt + 1) & 1);
        asm volatile("cp.async.commit_group;" ::: "memory");

        const uint32_t sb = (uint32_t)__cvta_generic_to_shared(smd + (kt & 1) * BSTG);

#pragma unroll
        for (int ks = 0; ks < 2; ++ks) {
            unsigned ah[2][4], al[2][4];
#pragma unroll
            for (int i = 0; i < 2; ++i) {
                uint32_t ad = sb + ((aRow + i * 16) * 40 + ks * 16 + aKof) * 2;
                ldsm4(ah[i], ad);
                ldsm4(al[i], ad + 10240);
            }
#pragma unroll
            for (int ng = 0; ng < 4; ++ng) {
                unsigned bh[4], bl[4];
                uint32_t bd = sb + 20480 +
                              ((bRow + ks * 16) * 136 + wn + ng * 16 + bNof) * 2;
                ldsm4t(bh, bd);
                ldsm4t(bl, bd + 8704);
#pragma unroll
                for (int jj = 0; jj < 2; ++jj) {
                    const int j = ng * 2 + jj;
#pragma unroll
                    for (int i = 0; i < 2; ++i) {
                        mma16(c[i][j], ah[i], bh[jj * 2], bh[jj * 2 + 1]);
                        mma16(c[i][j], ah[i], bl[jj * 2], bl[jj * 2 + 1]);
                        mma16(c[i][j], al[i], bh[jj * 2], bh[jj * 2 + 1]);
                    }
                }
            }
        }
    }

    // ---- epilogue ----
    const int gq = lane >> 2, tq = lane & 3;
#pragma unroll
    for (int i = 0; i < 2; ++i) {
        const int r0 = m0 + wm + i * 16 + gq;
#pragma unroll
        for (int j = 0; j < 8; ++j) {
            const int ccn = n0 + wn + j * 8 + 2 * tq;
            if (ccn >= N) continue;
            if (EPI == 0) {
                float* Cz = C + (long)blockIdx.z * (long)M * ldc;
                *(float2*)&Cz[(long)r0 * ldc + ccn] =
                    make_float2(c[i][j][0], c[i][j][1]);
                *(float2*)&Cz[(long)(r0 + 8) * ldc + ccn] =
                    make_float2(c[i][j][2], c[i][j][3]);
            } else {
#pragma unroll
                for (int rr = 0; rr < 2; ++rr) {
                    const long idx = (long)(r0 + rr * 8) * ldc + ccn;
                    float a0 = c[i][j][rr * 2 + 0], a1 = c[i][j][rr * 2 + 1];
                    float2 qv = *(const float2*)&Qp[idx];
                    float2 uv = *(const float2*)&Up[idx];
                    __nv_bfloat162 vh2 = *(const __nv_bfloat162*)&Vh[idx];
                    __nv_bfloat162 vl2 = *(const __nv_bfloat162*)&Vl[idx];
                    float2 un;
                    __nv_bfloat162 nh, nl;
                    {
                        float v = __bfloat162float(vh2.x) + __bfloat162float(vl2.x);
                        float x = qv.x + v - a0;
                        float z = fmaxf(x + uv.x - THR_F, 0.f);
                        un.x = uv.x + x - z;
                        float vn = is_last ? z : (2.f * z - uv.x - x);
                        split_bf16(vn, nh.x, nl.x);
                    }
                    {
                        float v = __bfloat162float(vh2.y) + __bfloat162float(vl2.y);
                        float x = qv.y + v - a1;
                        float z = fmaxf(x + uv.y - THR_F, 0.f);
                        un.y = uv.y + x - z;
                        float vn = is_last ? z : (2.f * z - uv.y - x);
                        split_bf16(vn, nh.y, nl.y);
                    }
                    *(float2*)&Up[idx] = un;
                    *(__nv_bfloat162*)&Vh[idx] = nh;
                    *(__nv_bfloat162*)&Vl[idx] = nl;
                }
            }
        }
    }
}

// ---------------------------------------------------------------------------
// SIMT tiled SGEMM (setup path only -- full fp32 accuracy)
// ---------------------------------------------------------------------------
#define BM 128
#define BN 128
#define BKK 16

template<bool TA, bool TB, int EPI>
__global__ void __launch_bounds__(256, 2)
gemm_kernel(const float* __restrict__ A, const float* __restrict__ B,
            float* __restrict__ C,
            int M, int N, int Kslice, int lda, int ldb, int ldc,
            const float* __restrict__ Qp)
{
    __shared__ float As[BKK][BM + 4];
    __shared__ float Bs[BKK][BN + 4];

    const int tid = threadIdx.x;
    const int tx  = tid & 15;
    const int ty  = tid >> 4;
    const int m0  = blockIdx.y * BM;
    const int n0  = blockIdx.x * BN;

    const long k0 = (long)blockIdx.z * Kslice;
    if (TA) A += k0 * lda; else A += k0;
    if (TB) B += k0;       else B += k0 * ldb;
    if (EPI == 0) C += (long)blockIdx.z * (long)M * ldc;

    float acc[8][8];
#pragma unroll
    for (int i = 0; i < 8; ++i)
#pragma unroll
        for (int j = 0; j < 8; ++j) acc[i][j] = 0.0f;

    const int nk = Kslice / BKK;
#pragma unroll 1
    for (int kt = 0; kt < nk; ++kt) {
        const int kbase = kt * BKK;
        if (!TA) {
#pragma unroll
            for (int p = 0; p < 2; ++p) {
                const int row = p * 64 + (tid >> 2);
                const int c4  = (tid & 3) * 4;
                float4 v = *(const float4*)&A[(long)(m0 + row) * lda + kbase + c4];
                As[c4 + 0][row] = v.x; As[c4 + 1][row] = v.y;
                As[c4 + 2][row] = v.z; As[c4 + 3][row] = v.w;
            }
        } else {
#pragma unroll
            for (int p = 0; p < 2; ++p) {
                const int kr = p * 8 + (tid >> 5);
                const int m4 = (tid & 31) * 4;
                float4 v = *(const float4*)&A[(long)(kbase + kr) * lda + m0 + m4];
                *(float4*)&As[kr][m4] = v;
            }
        }
        if (!TB) {
#pragma unroll
            for (int p = 0; p < 2; ++p) {
                const int kr  = p * 8 + (tid >> 5);
                const int nn4 = (tid & 31) * 4;
                const int gn  = n0 + nn4;
                float4 v = make_float4(0.f, 0.f, 0.f, 0.f);
                if (gn < N) v = *(const float4*)&B[(long)(kbase + kr) * ldb + gn];
                *(float4*)&Bs[kr][nn4] = v;
            }
        } else {
#pragma unroll
            for (int p = 0; p < 2; ++p) {
                const int nrow = p * 64 + (tid >> 2);
                const int c4   = (tid & 3) * 4;
                const int gn   = n0 + nrow;
                float4 v = make_float4(0.f, 0.f, 0.f, 0.f);
                if (gn < N) v = *(const float4*)&B[(long)gn * ldb + kbase + c4];
                Bs[c4 + 0][nrow] = v.x; Bs[c4 + 1][nrow] = v.y;
                Bs[c4 + 2][nrow] = v.z; Bs[c4 + 3][nrow] = v.w;
            }
        }
        __syncthreads();
#pragma unroll
        for (int kk = 0; kk < BKK; ++kk) {
            float a[8], b[8];
            *(float4*)&a[0] = *(const float4*)&As[kk][ty * 4];
            *(float4*)&a[4] = *(const float4*)&As[kk][64 + ty * 4];
            *(float4*)&b[0] = *(const float4*)&Bs[kk][tx * 4];
            *(float4*)&b[4] = *(const float4*)&Bs[kk][64 + tx * 4];
#pragma unroll
            for (int i = 0; i < 8; ++i)
#pragma unroll
                for (int j = 0; j < 8; ++j)
                    acc[i][j] = fmaf(a[i], b[j], acc[i][j]);
        }
        __syncthreads();
    }

    int rows[8];
#pragma unroll
    for (int i = 0; i < 8; ++i)
        rows[i] = m0 + (i < 4 ? ty * 4 + i : 64 + ty * 4 + (i - 4));

#pragma unroll
    for (int i = 0; i < 8; ++i) {
#pragma unroll
        for (int jg = 0; jg < 2; ++jg) {
            const int cn = n0 + jg * 64 + tx * 4;
            if (cn >= N) continue;
            const long idx = (long)rows[i] * ldc + cn;
            float a0 = acc[i][jg * 4 + 0], a1 = acc[i][jg * 4 + 1];
            float a2 = acc[i][jg * 4 + 2], a3 = acc[i][jg * 4 + 3];
            if (EPI == 0) {
                *(float4*)&C[idx] = make_float4(a0, a1, a2, a3);
            } else { // EPI 1: q = (Aty - acc) / rho
                float4 q = *(const float4*)&Qp[idx];
                const float ir = 1.0f / RHO_F;
                *(float4*)&C[idx] = make_float4((q.x - a0) * ir, (q.y - a1) * ir,
                                                (q.z - a2) * ir, (q.w - a3) * ir);
            }
        }
    }
}

// ---------------------------------------------------------------------------
// Reductions / splits
// ---------------------------------------------------------------------------
__global__ void reduce_sum(const float4* __restrict__ P, float4* __restrict__ out,
                           int n4, int S)
{
    int i = blockIdx.x * blockDim.x + threadIdx.x;
    if (i >= n4) return;
    float4 s = P[i];
    for (int k = 1; k < S; ++k) {
        float4 t = P[(long)k * n4 + i];
        s.x += t.x; s.y += t.y; s.z += t.z; s.w += t.w;
    }
    out[i] = s;
}

// split-K reduce -> bf16 hi/lo pair outputs
__global__ void reduce_split_k(const float2* __restrict__ P,
                               __nv_bfloat162* __restrict__ Wh,
                               __nv_bfloat162* __restrict__ Wl,
                               int n2, int S)
{
    int i = blockIdx.x * blockDim.x + threadIdx.x;
    if (i >= n2) return;
    float2 s = P[i];
    for (int k = 1; k < S; ++k) {
        float2 t = P[(long)k * n2 + i];
        s.x += t.x; s.y += t.y;
    }
    __nv_bfloat162 h, l;
    split_bf16(s.x, h.x, l.x);
    split_bf16(s.y, h.y, l.y);
    Wh[i] = h; Wl[i] = l;
}

__global__ void split_mat_bf16(const float2* __restrict__ src,
                               __nv_bfloat162* __restrict__ hi,
                               __nv_bfloat162* __restrict__ lo, long n2)
{
    long i = (long)blockIdx.x * blockDim.x + threadIdx.x;
    if (i >= n2) return;
    float2 v = src[i];
    __nv_bfloat162 h, l;
    split_bf16(v.x, h.x, l.x);
    split_bf16(v.y, h.y, l.y);
    hi[i] = h; lo[i] = l;
}

__global__ void reduce_G(const float* __restrict__ P, float* __restrict__ G, int S)
{
    int i = blockIdx.x * blockDim.x + threadIdx.x;
    if (i >= DM * DM) return;
    float s = 0.f;
    for (int k = 0; k < S; ++k) s += P[(long)k * DM * DM + i];
    if ((i / DM) == (i % DM)) s += RHO_F;
    G[i] = s;
}

__global__ void reduce_ns(const float4* __restrict__ P, const float4* __restrict__ Xc,
                          float4* __restrict__ Xn, int n4, int S)
{
    int i = blockIdx.x * blockDim.x + threadIdx.x;
    if (i >= n4) return;
    float4 s = P[i];
    for (int k = 1; k < S; ++k) {
        float4 t = P[(long)k * n4 + i];
        s.x += t.x; s.y += t.y; s.z += t.z; s.w += t.w;
    }
    float4 x = Xc[i];
    Xn[i] = make_float4(2.f * x.x - s.x, 2.f * x.y - s.y,
                        2.f * x.z - s.z, 2.f * x.w - s.w);
}

__global__ void ninf_kernel(const float* __restrict__ G)
{
    __shared__ float sm[DM];
    const int i = threadIdx.x;
    float s = 0.f;
    for (int j = 0; j < DM; ++j) s += fabsf(G[(long)j * DM + i]);
    sm[i] = s;
    __syncthreads();
    for (int o = DM / 2; o > 0; o >>= 1) {
        if (i < o) sm[i] = fmaxf(sm[i], sm[i + o]);
        __syncthreads();
    }
    if (i == 0) g_ninf = sm[0];
}

__global__ void x0_kernel(float* __restrict__ X)
{
    int i = blockIdx.x * blockDim.x + threadIdx.x;
    if (i >= DM * DM) return;
    float c = 2.0f / (RHO_F + g_ninf);
    X[i] = ((i / DM) == (i % DM)) ? c : 0.0f;
}

// ---------------------------------------------------------------------------
// Row-normalize kernels
// ---------------------------------------------------------------------------
__device__ __forceinline__ float block_sum128(float v, float* red)
{
    for (int o = 16; o > 0; o >>= 1) v += __shfl_xor_sync(0xffffffff, v, o);
    if ((threadIdx.x & 31) == 0) red[threadIdx.x >> 5] = v;
    __syncthreads();
    float tot = red[0] + red[1] + red[2] + red[3];
    __syncthreads();
    return tot;
}

__global__ void norm_center_kernel(const float* __restrict__ img,
                                   const float* __restrict__ mean,
                                   float* __restrict__ out)
{
    __shared__ float red[4];
    const int r = blockIdx.x, t = threadIdx.x;
    float4 v = ((const float4*)(img + (long)r * DM))[t];
    float ss = v.x * v.x + v.y * v.y + v.z * v.z + v.w * v.w;
    float inv = 1.0f / fmaxf(sqrtf(block_sum128(ss, red)), EPS_F);
    float4 mv = ((const float4*)mean)[t];
    float4 c = make_float4(v.x * inv - mv.x, v.y * inv - mv.y,
                           v.z * inv - mv.z, v.w * inv - mv.w);
    float ss2 = c.x * c.x + c.y * c.y + c.z * c.z + c.w * c.w;
    float inv2 = 1.0f / fmaxf(sqrtf(block_sum128(ss2, red)), EPS_F);
    ((float4*)(out + (long)r * DM))[t] =
        make_float4(c.x * inv2, c.y * inv2, c.z * inv2, c.w * inv2);
}

__global__ void norm_rows_kernel(const float* __restrict__ in, float* __restrict__ out)
{
    __shared__ float red[4];
    const int r = blockIdx.x, t = threadIdx.x;
    float4 v = ((const float4*)(in + (long)r * DM))[t];
    float ss = v.x * v.x + v.y * v.y + v.z * v.z + v.w * v.w;
    float inv = 1.0f / fmaxf(sqrtf(block_sum128(ss, red)), EPS_F);
    ((float4*)(out + (long)r * DM))[t] =
        make_float4(v.x * inv, v.y * inv, v.z * inv, v.w * inv);
}

__global__ void final_norm_kernel(const float* __restrict__ rec,
                                  const float* __restrict__ mean,
                                  float* __restrict__ out)
{
    __shared__ float red[4];
    const int r = blockIdx.x, t = threadIdx.x;
    float4 v = ((const float4*)(rec + (long)r * DM))[t];
    float ss = v.x * v.x + v.y * v.y + v.z * v.z + v.w * v.w;
    float inv = 1.0f / fmaxf(sqrtf(block_sum128(ss, red)), EPS_F);
    float4 mv = ((const float4*)mean)[t];
    float4 c = make_float4(v.x * inv + mv.x, v.y * inv + mv.y,
                           v.z * inv + mv.z, v.w * inv + mv.w);
    float ss2 = c.x * c.x + c.y * c.y + c.z * c.z + c.w * c.w;
    float inv2 = 1.0f / fmaxf(sqrtf(block_sum128(ss2, red)), EPS_F);
    ((float4*)(out + (long)r * DM))[t] =
        make_float4(c.x * inv2, c.y * inv2, c.z * inv2, c.w * inv2);
}

// ---------------------------------------------------------------------------
// Host orchestration
// ---------------------------------------------------------------------------
extern "C" void kernel_launch(void* const* d_in, const int* in_sizes, int n_in,
                              void* d_out, int out_size)
{
    const float* dImg  = (const float*)d_in[0];
    const float* dTxt  = (const float*)d_in[1];
    const float* dMean = (const float*)d_in[2];
    const float* dDict = (const float*)d_in[3];
    float* outRecon = (float*)d_out;
    float* outTxt   = (float*)d_out + (long)BROWS * DM;

    float *Q, *U, *E, *P, *W, *Y, *G, *XA, *XB, *T;
    __nv_bfloat16 *Vh, *Vl, *Dh, *Dl, *Eh, *El, *Wh, *Wl;
    cudaGetSymbolAddress((void**)&Q,  g_Q);
    cudaGetSymbolAddress((void**)&U,  g_U);
    cudaGetSymbolAddress((void**)&Vh, g_Vh);
    cudaGetSymbolAddress((void**)&Vl, g_Vl);
    cudaGetSymbolAddress((void**)&Dh, g_Dh);
    cudaGetSymbolAddress((void**)&Dl, g_Dl);
    cudaGetSymbolAddress((void**)&E,  g_E);
    cudaGetSymbolAddress((void**)&Eh, g_Eh);
    cudaGetSymbolAddress((void**)&El, g_El);
    cudaGetSymbolAddress((void**)&P,  g_P);
    cudaGetSymbolAddress((void**)&W,  g_W);
    cudaGetSymbolAddress((void**)&Wh, g_Wh);
    cudaGetSymbolAddress((void**)&Wl, g_Wl);
    cudaGetSymbolAddress((void**)&Y,  g_Y);
    cudaGetSymbolAddress((void**)&G,  g_G);
    cudaGetSymbolAddress((void**)&XA, g_XA);
    cudaGetSymbolAddress((void**)&XB, g_XB);
    cudaGetSymbolAddress((void**)&T,  g_T);

    cudaFuncSetAttribute(bmma_gemm<0>, cudaFuncAttributeMaxDynamicSharedMemorySize,
                         BSMEM);
    cudaFuncSetAttribute(bmma_gemm<2>, cudaFuncAttributeMaxDynamicSharedMemorySize,
                         BSMEM);

    const int NT = (CDICT + BN - 1) / BN;   // 79 tiles over N=10000
    const int KSsetup = CDICT / 5;          // 2000 (SIMT setup split-K)
    const int KSmma   = CPAD / KSPLIT;      // 2048 (bf16 loop split-K)

    // 1) centered inputs + text output
    norm_center_kernel<<<BROWS, 128>>>(dImg, dMean, Y);
    norm_rows_kernel<<<BROWS, 128>>>(dTxt, outTxt);

    // 2) Aty = Y @ D^T  -> Q  (ld = CPAD)
    gemm_kernel<false, true, 0><<<dim3(NT, 8, 1), 256>>>(
        Y, dDict, Q, BROWS, CDICT, DM, DM, DM, CPAD, nullptr);

    // 3) G = D^T D + rho I
    gemm_kernel<true, false, 0><<<dim3(4, 4, 5), 256>>>(
        dDict, dDict, P, DM, DM, KSsetup, DM, DM, DM, nullptr);
    reduce_G<<<(DM * DM + 255) / 256, 256>>>(P, G, 5);

    // 4) Newton-Schulz inverse
    ninf_kernel<<<1, DM>>>(G);
    x0_kernel<<<(DM * DM + 255) / 256, 256>>>(XA);
    float* Xc = XA; float* Xn = XB;
    for (int t = 0; t < NS_ITERS; ++t) {
        gemm_kernel<false, false, 0><<<dim3(4, 4, 4), 256>>>(
            G, Xc, P, DM, DM, DM / 4, DM, DM, DM, nullptr);
        reduce_sum<<<(DM * DM / 4 + 255) / 256, 256>>>(
            (const float4*)P, (float4*)T, DM * DM / 4, 4);
        gemm_kernel<false, false, 0><<<dim3(4, 4, 4), 256>>>(
            Xc, T, P, DM, DM, DM / 4, DM, DM, DM, nullptr);
        reduce_ns<<<(DM * DM / 4 + 255) / 256, 256>>>(
            (const float4*)P, (const float4*)Xc, (float4*)Xn, DM * DM / 4, 4);
        float* tmp = Xc; Xc = Xn; Xn = tmp;
    }

    // 5) E = G^{-1} @ D^T  (ld = CPAD; pad cols stay zero)
    gemm_kernel<false, true, 0><<<dim3(NT, 4, 1), 256>>>(
        Xc, dDict, E, DM, CDICT, DM, DM, DM, CPAD, nullptr);

    // bf16 splits: D (first CDICT rows of [CPAD x 512]) and E (full [512 x CPAD])
    split_mat_bf16<<<(int)(((long)CDICT * DM / 2 + 255) / 256), 256>>>(
        (const float2*)dDict, (__nv_bfloat162*)Dh, (__nv_bfloat162*)Dl,
        (long)CDICT * DM / 2);
    split_mat_bf16<<<(int)(((long)DM * CPAD / 2 + 255) / 256), 256>>>(
        (const float2*)E, (__nv_bfloat162*)Eh, (__nv_bfloat162*)El,
        (long)DM * CPAD / 2);

    // 6) q = (Aty - (Aty @ D) @ E) / rho  (fp32 SIMT, in place on Q)
    gemm_kernel<false, false, 0><<<dim3(4, 8, 5), 256>>>(
        Q, dDict, P, BROWS, DM, KSsetup, CPAD, DM, DM, nullptr);
    reduce_sum<<<(BROWS * DM / 4 + 255) / 256, 256>>>(
        (const float4*)P, (float4*)W, BROWS * DM / 4, 5);
    gemm_kernel<false, false, 1><<<dim3(NT, 8, 1), 256>>>(
        W, E, Q, BROWS, CDICT, DM, DM, CPAD, CPAD, Q);

    // 7) ADMM loop (bf16x3 tensor-core path).  Pad cols of Vh/Vl stay zero.
    cudaMemsetAsync(Vh, 0, sizeof(__nv_bfloat16) * (size_t)BROWS * CPAD, 0);
    cudaMemsetAsync(Vl, 0, sizeof(__nv_bfloat16) * (size_t)BROWS * CPAD, 0);
    cudaMemsetAsync(U,  0, sizeof(float) * (size_t)BROWS * CPAD, 0);
    for (int it = 0; it < ADMM_ITERS; ++it) {
        // w = v @ D    [1024 x 512], K = CPAD split 5 ways
        bmma_gemm<0><<<dim3(4, 8, KSPLIT), 256, BSMEM>>>(
            Vh, Vl, Dh, Dl, P, BROWS, DM, KSmma, CPAD, DM, DM,
            nullptr, nullptr, nullptr, nullptr, 0);
        reduce_split_k<<<(BROWS * DM / 2 + 255) / 256, 256>>>(
            (const float2*)P, (__nv_bfloat162*)Wh, (__nv_bfloat162*)Wl,
            BROWS * DM / 2, KSPLIT);
        // fused: acc = w @ E; ADMM update on (v, u)
        bmma_gemm<2><<<dim3(NT, 8, 1), 256, BSMEM>>>(
            Wh, Wl, Eh, El, nullptr, BROWS, CDICT, DM, DM, CPAD, CPAD,
            Q, U, Vh, Vl, (it == ADMM_ITERS - 1) ? 1 : 0);
    }

    // 8) recon = normalize(normalize(z @ D) + mean)   (z in Vh/Vl)
    bmma_gemm<0><<<dim3(4, 8, KSPLIT), 256, BSMEM>>>(
        Vh, Vl, Dh, Dl, P, BROWS, DM, KSmma, CPAD, DM, DM,
        nullptr, nullptr, nullptr, nullptr, 0);
    reduce_sum<<<(BROWS * DM / 4 + 255) / 256, 256>>>(
        (const float4*)P, (float4*)W, BROWS * DM / 4, KSPLIT);
    final_norm_kernel<<<BROWS, 128>>>(W, dMean, outRecon);
}

// round 6
// speedup vs baseline: 2.5725x; 1.1802x over previous
#include <cuda_runtime.h>
#include <cuda_bf16.h>
#include <math.h>
#include <stdint.h>

// ---------------------------------------------------------------------------
// Problem constants
// ---------------------------------------------------------------------------
#define BROWS 1024      // batch
#define CDICT 10000     // dictionary atoms
#define CPAD  10240     // padded dict dim: divisible by 128
#define DM    512       // embedding dim
#define RHO_F 5.0f
#define THR_F 0.002f    // lam / rho
#define EPS_F 1e-12f
#define ADMM_ITERS 100
#define NS_ITERS 9
#define KSPLIT 4        // loop split-K: 4*32 tiles = 128 CTAs <= 148 SMs (balanced)
#define PSLICES 5       // partial-buffer slices (setup path uses 5)

// ---------------------------------------------------------------------------
// Scratch (static device globals -- no cudaMalloc allowed)
// ---------------------------------------------------------------------------
__device__ float          g_Q [(size_t)BROWS * CPAD];   // Aty, then q  (ld=CPAD)
__device__ float          g_U [(size_t)BROWS * CPAD];   // u            (ld=CPAD)
__device__ __nv_bfloat16  g_Vh[(size_t)BROWS * CPAD];   // bf16-hi of v
__device__ __nv_bfloat16  g_Vl[(size_t)BROWS * CPAD];   // bf16-lo of v
__device__ __nv_bfloat16  g_Dh[(size_t)CPAD * DM];      // dict hi [CPAD x 512]
__device__ __nv_bfloat16  g_Dl[(size_t)CPAD * DM];
__device__ float          g_E [(size_t)DM * CPAD];      // E = G^{-1} D^T (fp32, ld=CPAD)
__device__ __nv_bfloat16  g_Eh[(size_t)DM * CPAD];
__device__ __nv_bfloat16  g_El[(size_t)DM * CPAD];
__device__ float          g_P [(size_t)PSLICES * BROWS * DM]; // split-K partials
__device__ float          g_W [(size_t)BROWS * DM];
__device__ __nv_bfloat16  g_Wh[(size_t)BROWS * DM];
__device__ __nv_bfloat16  g_Wl[(size_t)BROWS * DM];
__device__ float          g_Y [(size_t)BROWS * DM];
__device__ float g_G [DM * DM];
__device__ float g_XA[DM * DM];
__device__ float g_XB[DM * DM];
__device__ float g_T [DM * DM];
__device__ float g_ninf;

// ---------------------------------------------------------------------------
// helpers
// ---------------------------------------------------------------------------
__device__ __forceinline__ void split_bf16(float v, __nv_bfloat16& h, __nv_bfloat16& l)
{
    h = __float2bfloat16_rn(v);
    l = __float2bfloat16_rn(v - __bfloat162float(h));
}

__device__ __forceinline__ void mma16(float* c, const unsigned* a,
                                      unsigned b0, unsigned b1)
{
    asm volatile(
        "mma.sync.aligned.m16n8k16.row.col.f32.bf16.bf16.f32 "
        "{%0,%1,%2,%3}, {%4,%5,%6,%7}, {%8,%9}, {%0,%1,%2,%3};"
        : "+f"(c[0]), "+f"(c[1]), "+f"(c[2]), "+f"(c[3])
        : "r"(a[0]), "r"(a[1]), "r"(a[2]), "r"(a[3]), "r"(b0), "r"(b1));
}

__device__ __forceinline__ void ldsm4(unsigned* r, uint32_t a)
{
    asm volatile("ldmatrix.sync.aligned.m8n8.x4.shared.b16 {%0,%1,%2,%3}, [%4];"
                 : "=r"(r[0]), "=r"(r[1]), "=r"(r[2]), "=r"(r[3]) : "r"(a));
}

__device__ __forceinline__ void ldsm4t(unsigned* r, uint32_t a)
{
    asm volatile("ldmatrix.sync.aligned.m8n8.x4.trans.shared.b16 {%0,%1,%2,%3}, [%4];"
                 : "=r"(r[0]), "=r"(r[1]), "=r"(r[2]), "=r"(r[3]) : "r"(a));
}

__device__ __forceinline__ void cp16(uint32_t s, const void* g)
{
    asm volatile("cp.async.cg.shared.global [%0], [%1], 16;"
                 :: "r"(s), "l"(g) : "memory");
}

// ---------------------------------------------------------------------------
// bf16x3 MMA GEMM: C[M,N] = A[M,K] * B[K,N]; A,B pre-split (hi, lo) bf16.
// acc = Ah*Bh + Ah*Bl + Al*Bh  (fp32 accumulate).
// BM=BN=128, BK=32, 256 thr, 8 warps (warp tile 32x64), 2-stage cp.async.
// ldmatrix for all fragments (conflict-free strides 40 / 136 bf16).
// blockIdx.z = split-K slice; EPI 0 writes partial at C + z*M*ldc.
// EPI 2: fused ADMM: v=Vh+Vl; x=Q+v-acc; z=max(x+U-thr,0); U'=U+x-z;
//        vnew = is_last ? z : 2z-U-x; split vnew -> Vh,Vl (bf16).
// Stage layout (bytes): Ah[128][40]@0 (10240), Al@10240, Bh[32][136]@20480
// (8704), Bl@29184.  Stage = 37888 B, 2 stages = 75776 B dynamic smem.
// ---------------------------------------------------------------------------
#define BSTG  37888
#define BSMEM (2 * BSTG)

template<int EPI>
__global__ void __launch_bounds__(256, 2)
bmma_gemm(const __nv_bfloat16* __restrict__ Ah, const __nv_bfloat16* __restrict__ Al,
          const __nv_bfloat16* __restrict__ Bh, const __nv_bfloat16* __restrict__ Bl,
          float* __restrict__ C, int M, int N, int Kslice,
          int lda, int ldb, int ldc,
          const float* __restrict__ Qp, float* __restrict__ Up,
          __nv_bfloat16* __restrict__ Vh, __nv_bfloat16* __restrict__ Vl,
          int is_last)
{
    extern __shared__ char smd[];
    const int tid  = threadIdx.x;
    const int lane = tid & 31, wid = tid >> 5;
    const int wm = (wid & 3) * 32;
    const int wn = (wid >> 2) * 64;
    const int m0 = blockIdx.y * 128, n0 = blockIdx.x * 128;
    const long k0 = (long)blockIdx.z * Kslice;
    const int nk = Kslice >> 5;

    // ldmatrix per-lane addressing
    const int aRow = wm + ((lane >> 3) & 1) * 8 + (lane & 7);
    const int aKof = (lane >> 4) * 8;
    const int bRow = ((lane >> 3) & 1) * 8 + (lane & 7);
    const int bNof = (lane >> 4) * 8;

    float c[2][8][4];
#pragma unroll
    for (int i = 0; i < 2; ++i)
#pragma unroll
        for (int j = 0; j < 8; ++j)
#pragma unroll
            for (int q = 0; q < 4; ++q) c[i][j][q] = 0.0f;

    auto load_tile = [&](int kt, int buf) {
        char* base = smd + buf * BSTG;
        const int kb = kt * 32;
#pragma unroll
        for (int cc = 0; cc < 2; ++cc) {        // A: 128 rows x 4 chunks (8 bf16)
            int ch  = tid * 2 + cc;
            int row = ch >> 2, kc = (ch & 3) * 8;
            uint32_t so = (uint32_t)__cvta_generic_to_shared(
                base + (row * 40 + kc) * 2);
            const long go = (long)(m0 + row) * lda + k0 + kb + kc;
            cp16(so,         Ah + go);
            cp16(so + 10240, Al + go);
        }
#pragma unroll
        for (int cc = 0; cc < 2; ++cc) {        // B: 32 rows x 16 chunks
            int ch  = tid * 2 + cc;
            int row = ch >> 4, nc = (ch & 15) * 8;
            uint32_t so = (uint32_t)__cvta_generic_to_shared(
                base + 20480 + (row * 136 + nc) * 2);
            const long go = (long)(k0 + kb + row) * ldb + n0 + nc;
            cp16(so,        Bh + go);
            cp16(so + 8704, Bl + go);
        }
    };

    load_tile(0, 0);
    asm volatile("cp.async.commit_group;" ::: "memory");

    for (int kt = 0; kt < nk; ++kt) {
        asm volatile("cp.async.wait_group 0;" ::: "memory");
        __syncthreads();
        if (kt + 1 < nk) load_tile(kt + 1, (kt + 1) & 1);
        asm volatile("cp.async.commit_group;" ::: "memory");

        const uint32_t sb = (uint32_t)__cvta_generic_to_shared(smd + (kt & 1) * BSTG);

#pragma unroll
        for (int ks = 0; ks < 2; ++ks) {
            unsigned ah[2][4], al[2][4];
#pragma unroll
            for (int i = 0; i < 2; ++i) {
                uint32_t ad = sb + ((aRow + i * 16) * 40 + ks * 16 + aKof) * 2;
                ldsm4(ah[i], ad);
                ldsm4(al[i], ad + 10240);
            }
#pragma unroll
            for (int ng = 0; ng < 4; ++ng) {
                unsigned bh[4], bl[4];
                uint32_t bd = sb + 20480 +
                              ((bRow + ks * 16) * 136 + wn + ng * 16 + bNof) * 2;
                ldsm4t(bh, bd);
                ldsm4t(bl, bd + 8704);
#pragma unroll
                for (int jj = 0; jj < 2; ++jj) {
                    const int j = ng * 2 + jj;
#pragma unroll
                    for (int i = 0; i < 2; ++i) {
                        mma16(c[i][j], ah[i], bh[jj * 2], bh[jj * 2 + 1]);
                        mma16(c[i][j], ah[i], bl[jj * 2], bl[jj * 2 + 1]);
                        mma16(c[i][j], al[i], bh[jj * 2], bh[jj * 2 + 1]);
                    }
                }
            }
        }
    }

    // ---- epilogue ----
    const int gq = lane >> 2, tq = lane & 3;
#pragma unroll
    for (int i = 0; i < 2; ++i) {
        const int r0 = m0 + wm + i * 16 + gq;
#pragma unroll
        for (int j = 0; j < 8; ++j) {
            const int ccn = n0 + wn + j * 8 + 2 * tq;
            if (ccn >= N) continue;
            if (EPI == 0) {
                float* Cz = C + (long)blockIdx.z * (long)M * ldc;
                *(float2*)&Cz[(long)r0 * ldc + ccn] =
                    make_float2(c[i][j][0], c[i][j][1]);
                *(float2*)&Cz[(long)(r0 + 8) * ldc + ccn] =
                    make_float2(c[i][j][2], c[i][j][3]);
            } else {
#pragma unroll
                for (int rr = 0; rr < 2; ++rr) {
                    const long idx = (long)(r0 + rr * 8) * ldc + ccn;
                    float a0 = c[i][j][rr * 2 + 0], a1 = c[i][j][rr * 2 + 1];
                    float2 qv = *(const float2*)&Qp[idx];
                    float2 uv = *(const float2*)&Up[idx];
                    __nv_bfloat162 vh2 = *(const __nv_bfloat162*)&Vh[idx];
                    __nv_bfloat162 vl2 = *(const __nv_bfloat162*)&Vl[idx];
                    float2 un;
                    __nv_bfloat162 nh, nl;
                    {
                        float v = __bfloat162float(vh2.x) + __bfloat162float(vl2.x);
                        float x = qv.x + v - a0;
                        float z = fmaxf(x + uv.x - THR_F, 0.f);
                        un.x = uv.x + x - z;
                        float vn = is_last ? z : (2.f * z - uv.x - x);
                        split_bf16(vn, nh.x, nl.x);
                    }
                    {
                        float v = __bfloat162float(vh2.y) + __bfloat162float(vl2.y);
                        float x = qv.y + v - a1;
                        float z = fmaxf(x + uv.y - THR_F, 0.f);
                        un.y = uv.y + x - z;
                        float vn = is_last ? z : (2.f * z - uv.y - x);
                        split_bf16(vn, nh.y, nl.y);
                    }
                    *(float2*)&Up[idx] = un;
                    *(__nv_bfloat162*)&Vh[idx] = nh;
                    *(__nv_bfloat162*)&Vl[idx] = nl;
                }
            }
        }
    }
}

// ---------------------------------------------------------------------------
// SIMT tiled SGEMM (setup path only -- full fp32 accuracy)
// ---------------------------------------------------------------------------
#define BM 128
#define BN 128
#define BKK 16

template<bool TA, bool TB, int EPI>
__global__ void __launch_bounds__(256, 2)
gemm_kernel(const float* __restrict__ A, const float* __restrict__ B,
            float* __restrict__ C,
            int M, int N, int Kslice, int lda, int ldb, int ldc,
            const float* __restrict__ Qp)
{
    __shared__ float As[BKK][BM + 4];
    __shared__ float Bs[BKK][BN + 4];

    const int tid = threadIdx.x;
    const int tx  = tid & 15;
    const int ty  = tid >> 4;
    const int m0  = blockIdx.y * BM;
    const int n0  = blockIdx.x * BN;

    const long k0 = (long)blockIdx.z * Kslice;
    if (TA) A += k0 * lda; else A += k0;
    if (TB) B += k0;       else B += k0 * ldb;
    if (EPI == 0) C += (long)blockIdx.z * (long)M * ldc;

    float acc[8][8];
#pragma unroll
    for (int i = 0; i < 8; ++i)
#pragma unroll
        for (int j = 0; j < 8; ++j) acc[i][j] = 0.0f;

    const int nk = Kslice / BKK;
#pragma unroll 1
    for (int kt = 0; kt < nk; ++kt) {
        const int kbase = kt * BKK;
        if (!TA) {
#pragma unroll
            for (int p = 0; p < 2; ++p) {
                const int row = p * 64 + (tid >> 2);
                const int c4  = (tid & 3) * 4;
                float4 v = *(const float4*)&A[(long)(m0 + row) * lda + kbase + c4];
                As[c4 + 0][row] = v.x; As[c4 + 1][row] = v.y;
                As[c4 + 2][row] = v.z; As[c4 + 3][row] = v.w;
            }
        } else {
#pragma unroll
            for (int p = 0; p < 2; ++p) {
                const int kr = p * 8 + (tid >> 5);
                const int m4 = (tid & 31) * 4;
                float4 v = *(const float4*)&A[(long)(kbase + kr) * lda + m0 + m4];
                *(float4*)&As[kr][m4] = v;
            }
        }
        if (!TB) {
#pragma unroll
            for (int p = 0; p < 2; ++p) {
                const int kr  = p * 8 + (tid >> 5);
                const int nn4 = (tid & 31) * 4;
                const int gn  = n0 + nn4;
                float4 v = make_float4(0.f, 0.f, 0.f, 0.f);
                if (gn < N) v = *(const float4*)&B[(long)(kbase + kr) * ldb + gn];
                *(float4*)&Bs[kr][nn4] = v;
            }
        } else {
#pragma unroll
            for (int p = 0; p < 2; ++p) {
                const int nrow = p * 64 + (tid >> 2);
                const int c4   = (tid & 3) * 4;
                const int gn   = n0 + nrow;
                float4 v = make_float4(0.f, 0.f, 0.f, 0.f);
                if (gn < N) v = *(const float4*)&B[(long)gn * ldb + kbase + c4];
                Bs[c4 + 0][nrow] = v.x; Bs[c4 + 1][nrow] = v.y;
                Bs[c4 + 2][nrow] = v.z; Bs[c4 + 3][nrow] = v.w;
            }
        }
        __syncthreads();
#pragma unroll
        for (int kk = 0; kk < BKK; ++kk) {
            float a[8], b[8];
            *(float4*)&a[0] = *(const float4*)&As[kk][ty * 4];
            *(float4*)&a[4] = *(const float4*)&As[kk][64 + ty * 4];
            *(float4*)&b[0] = *(const float4*)&Bs[kk][tx * 4];
            *(float4*)&b[4] = *(const float4*)&Bs[kk][64 + tx * 4];
#pragma unroll
            for (int i = 0; i < 8; ++i)
#pragma unroll
                for (int j = 0; j < 8; ++j)
                    acc[i][j] = fmaf(a[i], b[j], acc[i][j]);
        }
        __syncthreads();
    }

    int rows[8];
#pragma unroll
    for (int i = 0; i < 8; ++i)
        rows[i] = m0 + (i < 4 ? ty * 4 + i : 64 + ty * 4 + (i - 4));

#pragma unroll
    for (int i = 0; i < 8; ++i) {
#pragma unroll
        for (int jg = 0; jg < 2; ++jg) {
            const int cn = n0 + jg * 64 + tx * 4;
            if (cn >= N) continue;
            const long idx = (long)rows[i] * ldc + cn;
            float a0 = acc[i][jg * 4 + 0], a1 = acc[i][jg * 4 + 1];
            float a2 = acc[i][jg * 4 + 2], a3 = acc[i][jg * 4 + 3];
            if (EPI == 0) {
                *(float4*)&C[idx] = make_float4(a0, a1, a2, a3);
            } else { // EPI 1: q = (Aty - acc) / rho
                float4 q = *(const float4*)&Qp[idx];
                const float ir = 1.0f / RHO_F;
                *(float4*)&C[idx] = make_float4((q.x - a0) * ir, (q.y - a1) * ir,
                                                (q.z - a2) * ir, (q.w - a3) * ir);
            }
        }
    }
}

// ---------------------------------------------------------------------------
// Reductions / splits
// ---------------------------------------------------------------------------
__global__ void reduce_sum(const float4* __restrict__ P, float4* __restrict__ out,
                           int n4, int S)
{
    int i = blockIdx.x * blockDim.x + threadIdx.x;
    if (i >= n4) return;
    float4 s = P[i];
    for (int k = 1; k < S; ++k) {
        float4 t = P[(long)k * n4 + i];
        s.x += t.x; s.y += t.y; s.z += t.z; s.w += t.w;
    }
    out[i] = s;
}

// split-K reduce -> bf16 hi/lo pair outputs
__global__ void reduce_split_k(const float2* __restrict__ P,
                               __nv_bfloat162* __restrict__ Wh,
                               __nv_bfloat162* __restrict__ Wl,
                               int n2, int S)
{
    int i = blockIdx.x * blockDim.x + threadIdx.x;
    if (i >= n2) return;
    float2 s = P[i];
    for (int k = 1; k < S; ++k) {
        float2 t = P[(long)k * n2 + i];
        s.x += t.x; s.y += t.y;
    }
    __nv_bfloat162 h, l;
    split_bf16(s.x, h.x, l.x);
    split_bf16(s.y, h.y, l.y);
    Wh[i] = h; Wl[i] = l;
}

__global__ void split_mat_bf16(const float2* __restrict__ src,
                               __nv_bfloat162* __restrict__ hi,
                               __nv_bfloat162* __restrict__ lo, long n2)
{
    long i = (long)blockIdx.x * blockDim.x + threadIdx.x;
    if (i >= n2) return;
    float2 v = src[i];
    __nv_bfloat162 h, l;
    split_bf16(v.x, h.x, l.x);
    split_bf16(v.y, h.y, l.y);
    hi[i] = h; lo[i] = l;
}

__global__ void reduce_G(const float* __restrict__ P, float* __restrict__ G, int S)
{
    int i = blockIdx.x * blockDim.x + threadIdx.x;
    if (i >= DM * DM) return;
    float s = 0.f;
    for (int k = 0; k < S; ++k) s += P[(long)k * DM * DM + i];
    if ((i / DM) == (i % DM)) s += RHO_F;
    G[i] = s;
}

__global__ void reduce_ns(const float4* __restrict__ P, const float4* __restrict__ Xc,
                          float4* __restrict__ Xn, int n4, int S)
{
    int i = blockIdx.x * blockDim.x + threadIdx.x;
    if (i >= n4) return;
    float4 s = P[i];
    for (int k = 1; k < S; ++k) {
        float4 t = P[(long)k * n4 + i];
        s.x += t.x; s.y += t.y; s.z += t.z; s.w += t.w;
    }
    float4 x = Xc[i];
    Xn[i] = make_float4(2.f * x.x - s.x, 2.f * x.y - s.y,
                        2.f * x.z - s.z, 2.f * x.w - s.w);
}

__global__ void ninf_kernel(const float* __restrict__ G)
{
    __shared__ float sm[DM];
    const int i = threadIdx.x;
    float s = 0.f;
    for (int j = 0; j < DM; ++j) s += fabsf(G[(long)j * DM + i]);
    sm[i] = s;
    __syncthreads();
    for (int o = DM / 2; o > 0; o >>= 1) {
        if (i < o) sm[i] = fmaxf(sm[i], sm[i + o]);
        __syncthreads();
    }
    if (i == 0) g_ninf = sm[0];
}

__global__ void x0_kernel(float* __restrict__ X)
{
    int i = blockIdx.x * blockDim.x + threadIdx.x;
    if (i >= DM * DM) return;
    float c = 2.0f / (RHO_F + g_ninf);
    X[i] = ((i / DM) == (i % DM)) ? c : 0.0f;
}

// ---------------------------------------------------------------------------
// Row-normalize kernels
// ---------------------------------------------------------------------------
__device__ __forceinline__ float block_sum128(float v, float* red)
{
    for (int o = 16; o > 0; o >>= 1) v += __shfl_xor_sync(0xffffffff, v, o);
    if ((threadIdx.x & 31) == 0) red[threadIdx.x >> 5] = v;
    __syncthreads();
    float tot = red[0] + red[1] + red[2] + red[3];
    __syncthreads();
    return tot;
}

__global__ void norm_center_kernel(const float* __restrict__ img,
                                   const float* __restrict__ mean,
                                   float* __restrict__ out)
{
    __shared__ float red[4];
    const int r = blockIdx.x, t = threadIdx.x;
    float4 v = ((const float4*)(img + (long)r * DM))[t];
    float ss = v.x * v.x + v.y * v.y + v.z * v.z + v.w * v.w;
    float inv = 1.0f / fmaxf(sqrtf(block_sum128(ss, red)), EPS_F);
    float4 mv = ((const float4*)mean)[t];
    float4 c = make_float4(v.x * inv - mv.x, v.y * inv - mv.y,
                           v.z * inv - mv.z, v.w * inv - mv.w);
    float ss2 = c.x * c.x + c.y * c.y + c.z * c.z + c.w * c.w;
    float inv2 = 1.0f / fmaxf(sqrtf(block_sum128(ss2, red)), EPS_F);
    ((float4*)(out + (long)r * DM))[t] =
        make_float4(c.x * inv2, c.y * inv2, c.z * inv2, c.w * inv2);
}

__global__ void norm_rows_kernel(const float* __restrict__ in, float* __restrict__ out)
{
    __shared__ float red[4];
    const int r = blockIdx.x, t = threadIdx.x;
    float4 v = ((const float4*)(in + (long)r * DM))[t];
    float ss = v.x * v.x + v.y * v.y + v.z * v.z + v.w * v.w;
    float inv = 1.0f / fmaxf(sqrtf(block_sum128(ss, red)), EPS_F);
    ((float4*)(out + (long)r * DM))[t] =
        make_float4(v.x * inv, v.y * inv, v.z * inv, v.w * inv);
}

__global__ void final_norm_kernel(const float* __restrict__ rec,
                                  const float* __restrict__ mean,
                                  float* __restrict__ out)
{
    __shared__ float red[4];
    const int r = blockIdx.x, t = threadIdx.x;
    float4 v = ((const float4*)(rec + (long)r * DM))[t];
    float ss = v.x * v.x + v.y * v.y + v.z * v.z + v.w * v.w;
    float inv = 1.0f / fmaxf(sqrtf(block_sum128(ss, red)), EPS_F);
    float4 mv = ((const float4*)mean)[t];
    float4 c = make_float4(v.x * inv + mv.x, v.y * inv + mv.y,
                           v.z * inv + mv.z, v.w * inv + mv.w);
    float ss2 = c.x * c.x + c.y * c.y + c.z * c.z + c.w * c.w;
    float inv2 = 1.0f / fmaxf(sqrtf(block_sum128(ss2, red)), EPS_F);
    ((float4*)(out + (long)r * DM))[t] =
        make_float4(c.x * inv2, c.y * inv2, c.z * inv2, c.w * inv2);
}

// ---------------------------------------------------------------------------
// Host orchestration
// ---------------------------------------------------------------------------
extern "C" void kernel_launch(void* const* d_in, const int* in_sizes, int n_in,
                              void* d_out, int out_size)
{
    const float* dImg  = (const float*)d_in[0];
    const float* dTxt  = (const float*)d_in[1];
    const float* dMean = (const float*)d_in[2];
    const float* dDict = (const float*)d_in[3];
    float* outRecon = (float*)d_out;
    float* outTxt   = (float*)d_out + (long)BROWS * DM;

    float *Q, *U, *E, *P, *W, *Y, *G, *XA, *XB, *T;
    __nv_bfloat16 *Vh, *Vl, *Dh, *Dl, *Eh, *El, *Wh, *Wl;
    cudaGetSymbolAddress((void**)&Q,  g_Q);
    cudaGetSymbolAddress((void**)&U,  g_U);
    cudaGetSymbolAddress((void**)&Vh, g_Vh);
    cudaGetSymbolAddress((void**)&Vl, g_Vl);
    cudaGetSymbolAddress((void**)&Dh, g_Dh);
    cudaGetSymbolAddress((void**)&Dl, g_Dl);
    cudaGetSymbolAddress((void**)&E,  g_E);
    cudaGetSymbolAddress((void**)&Eh, g_Eh);
    cudaGetSymbolAddress((void**)&El, g_El);
    cudaGetSymbolAddress((void**)&P,  g_P);
    cudaGetSymbolAddress((void**)&W,  g_W);
    cudaGetSymbolAddress((void**)&Wh, g_Wh);
    cudaGetSymbolAddress((void**)&Wl, g_Wl);
    cudaGetSymbolAddress((void**)&Y,  g_Y);
    cudaGetSymbolAddress((void**)&G,  g_G);
    cudaGetSymbolAddress((void**)&XA, g_XA);
    cudaGetSymbolAddress((void**)&XB, g_XB);
    cudaGetSymbolAddress((void**)&T,  g_T);

    cudaFuncSetAttribute(bmma_gemm<0>, cudaFuncAttributeMaxDynamicSharedMemorySize,
                         BSMEM);
    cudaFuncSetAttribute(bmma_gemm<2>, cudaFuncAttributeMaxDynamicSharedMemorySize,
                         BSMEM);

    const int NT = (CDICT + BN - 1) / BN;   // 79 tiles over N=10000
    const int KSsetup = CDICT / 5;          // 2000 (SIMT setup split-K, 5 slices)
    const int KSmma   = CPAD / KSPLIT;      // 2560 (bf16 loop split-K, 4 slices)

    // 1) centered inputs + text output
    norm_center_kernel<<<BROWS, 128>>>(dImg, dMean, Y);
    norm_rows_kernel<<<BROWS, 128>>>(dTxt, outTxt);

    // 2) Aty = Y @ D^T  -> Q  (ld = CPAD)
    gemm_kernel<false, true, 0><<<dim3(NT, 8, 1), 256>>>(
        Y, dDict, Q, BROWS, CDICT, DM, DM, DM, CPAD, nullptr);

    // 3) G = D^T D + rho I
    gemm_kernel<true, false, 0><<<dim3(4, 4, 5), 256>>>(
        dDict, dDict, P, DM, DM, KSsetup, DM, DM, DM, nullptr);
    reduce_G<<<(DM * DM + 255) / 256, 256>>>(P, G, 5);

    // 4) Newton-Schulz inverse (e0 ~ 0.905; e0^(2^9) ~ 5e-23 -> fp32 exact)
    ninf_kernel<<<1, DM>>>(G);
    x0_kernel<<<(DM * DM + 255) / 256, 256>>>(XA);
    float* Xc = XA; float* Xn = XB;
    for (int t = 0; t < NS_ITERS; ++t) {
        gemm_kernel<false, false, 0><<<dim3(4, 4, 4), 256>>>(
            G, Xc, P, DM, DM, DM / 4, DM, DM, DM, nullptr);
        reduce_sum<<<(DM * DM / 4 + 255) / 256, 256>>>(
            (const float4*)P, (float4*)T, DM * DM / 4, 4);
        gemm_kernel<false, false, 0><<<dim3(4, 4, 4), 256>>>(
            Xc, T, P, DM, DM, DM / 4, DM, DM, DM, nullptr);
        reduce_ns<<<(DM * DM / 4 + 255) / 256, 256>>>(
            (const float4*)P, (const float4*)Xc, (float4*)Xn, DM * DM / 4, 4);
        float* tmp = Xc; Xc = Xn; Xn = tmp;
    }

    // 5) E = G^{-1} @ D^T  (ld = CPAD; pad cols stay zero via memset below)
    cudaMemsetAsync(E, 0, sizeof(float) * (size_t)DM * CPAD, 0);
    gemm_kernel<false, true, 0><<<dim3(NT, 4, 1), 256>>>(
        Xc, dDict, E, DM, CDICT, DM, DM, DM, CPAD, nullptr);

    // bf16 splits: D (first CDICT rows of [CPAD x 512]) and E (full [512 x CPAD])
    cudaMemsetAsync(Dh, 0, sizeof(__nv_bfloat16) * (size_t)CPAD * DM, 0);
    cudaMemsetAsync(Dl, 0, sizeof(__nv_bfloat16) * (size_t)CPAD * DM, 0);
    split_mat_bf16<<<(int)(((long)CDICT * DM / 2 + 255) / 256), 256>>>(
        (const float2*)dDict, (__nv_bfloat162*)Dh, (__nv_bfloat162*)Dl,
        (long)CDICT * DM / 2);
    split_mat_bf16<<<(int)(((long)DM * CPAD / 2 + 255) / 256), 256>>>(
        (const float2*)E, (__nv_bfloat162*)Eh, (__nv_bfloat162*)El,
        (long)DM * CPAD / 2);

    // 6) q = (Aty - (Aty @ D) @ E) / rho  (fp32 SIMT, in place on Q)
    gemm_kernel<false, false, 0><<<dim3(4, 8, 5), 256>>>(
        Q, dDict, P, BROWS, DM, KSsetup, CPAD, DM, DM, nullptr);
    reduce_sum<<<(BROWS * DM / 4 + 255) / 256, 256>>>(
        (const float4*)P, (float4*)W, BROWS * DM / 4, 5);
    gemm_kernel<false, false, 1><<<dim3(NT, 8, 1), 256>>>(
        W, E, Q, BROWS, CDICT, DM, DM, CPAD, CPAD, Q);

    // 7) ADMM loop (bf16x3 tensor-core path).  Pad cols of Vh/Vl stay zero.
    cudaMemsetAsync(Vh, 0, sizeof(__nv_bfloat16) * (size_t)BROWS * CPAD, 0);
    cudaMemsetAsync(Vl, 0, sizeof(__nv_bfloat16) * (size_t)BROWS * CPAD, 0);
    cudaMemsetAsync(U,  0, sizeof(float) * (size_t)BROWS * CPAD, 0);
    for (int it = 0; it < ADMM_ITERS; ++it) {
        // w = v @ D  [1024 x 512], K = CPAD split 4 ways -> 128 CTAs (1/SM)
        bmma_gemm<0><<<dim3(4, 8, KSPLIT), 256, BSMEM>>>(
            Vh, Vl, Dh, Dl, P, BROWS, DM, KSmma, CPAD, DM, DM,
            nullptr, nullptr, nullptr, nullptr, 0);
        reduce_split_k<<<(BROWS * DM / 2 + 255) / 256, 256>>>(
            (const float2*)P, (__nv_bfloat162*)Wh, (__nv_bfloat162*)Wl,
            BROWS * DM / 2, KSPLIT);
        // fused: acc = w @ E; ADMM update on (v, u)
        bmma_gemm<2><<<dim3(NT, 8, 1), 256, BSMEM>>>(
            Wh, Wl, Eh, El, nullptr, BROWS, CDICT, DM, DM, CPAD, CPAD,
            Q, U, Vh, Vl, (it == ADMM_ITERS - 1) ? 1 : 0);
    }

    // 8) recon = normalize(normalize(z @ D) + mean)   (z in Vh/Vl)
    bmma_gemm<0><<<dim3(4, 8, KSPLIT), 256, BSMEM>>>(
        Vh, Vl, Dh, Dl, P, BROWS, DM, KSmma, CPAD, DM, DM,
        nullptr, nullptr, nullptr, nullptr, 0);
    reduce_sum<<<(BROWS * DM / 4 + 255) / 256, 256>>>(
        (const float4*)P, (float4*)W, BROWS * DM / 4, KSPLIT);
    final_norm_kernel<<<BROWS, 128>>>(W, dMean, outRecon);
}

// round 8
// speedup vs baseline: 3.3591x; 1.3058x over previous
#include <cuda_runtime.h>
#include <cuda_bf16.h>
#include <math.h>
#include <stdint.h>

// ---------------------------------------------------------------------------
// Problem constants
// ---------------------------------------------------------------------------
#define BROWS 1024      // batch
#define CDICT 10000     // dictionary atoms
#define CPAD  10240     // padded dict dim: divisible by 128
#define DM    512       // embedding dim
#define RHO_F 5.0f
#define THR_F 0.002f    // lam / rho
#define EPS_F 1e-12f
#define ADMM_ITERS 100
#define CHEAP_ITERS 80  // iters run with 1-product bf16; rest with 3-product split
#define NS_ITERS 9
#define KSPLIT 4        // loop split-K: 128 CTAs <= 148 SMs (balanced)
#define PSLICES 5

// ---------------------------------------------------------------------------
// Scratch (static device globals -- no cudaMalloc allowed)
// ---------------------------------------------------------------------------
__device__ float          g_Q [(size_t)BROWS * CPAD];   // Aty, then q  (ld=CPAD)
__device__ float          g_U [(size_t)BROWS * CPAD];   // u            (ld=CPAD)
__device__ __nv_bfloat16  g_Vh[(size_t)BROWS * CPAD];   // bf16-hi of v
__device__ __nv_bfloat16  g_Vl[(size_t)BROWS * CPAD];   // bf16-lo of v
__device__ __nv_bfloat16  g_Dh[(size_t)CPAD * DM];      // dict hi [CPAD x 512]
__device__ __nv_bfloat16  g_Dl[(size_t)CPAD * DM];
__device__ float          g_E [(size_t)DM * CPAD];      // E = G^{-1} D^T (fp32)
__device__ __nv_bfloat16  g_Eh[(size_t)DM * CPAD];
__device__ __nv_bfloat16  g_El[(size_t)DM * CPAD];
__device__ float          g_P [(size_t)PSLICES * BROWS * DM];
__device__ float          g_W [(size_t)BROWS * DM];
__device__ __nv_bfloat16  g_Wh[(size_t)BROWS * DM];
__device__ __nv_bfloat16  g_Wl[(size_t)BROWS * DM];
__device__ float          g_Y [(size_t)BROWS * DM];
__device__ float g_G [DM * DM];
__device__ float g_XA[DM * DM];
__device__ float g_XB[DM * DM];
__device__ float g_T [DM * DM];
__device__ float g_ninf;

// ---------------------------------------------------------------------------
// helpers
// ---------------------------------------------------------------------------
__device__ __forceinline__ void split_bf16(float v, __nv_bfloat16& h, __nv_bfloat16& l)
{
    h = __float2bfloat16_rn(v);
    l = __float2bfloat16_rn(v - __bfloat162float(h));
}

__device__ __forceinline__ void mma16(float* c, const unsigned* a,
                                      unsigned b0, unsigned b1)
{
    asm volatile(
        "mma.sync.aligned.m16n8k16.row.col.f32.bf16.bf16.f32 "
        "{%0,%1,%2,%3}, {%4,%5,%6,%7}, {%8,%9}, {%0,%1,%2,%3};"
        : "+f"(c[0]), "+f"(c[1]), "+f"(c[2]), "+f"(c[3])
        : "r"(a[0]), "r"(a[1]), "r"(a[2]), "r"(a[3]), "r"(b0), "r"(b1));
}

__device__ __forceinline__ void ldsm4(unsigned* r, uint32_t a)
{
    asm volatile("ldmatrix.sync.aligned.m8n8.x4.shared.b16 {%0,%1,%2,%3}, [%4];"
                 : "=r"(r[0]), "=r"(r[1]), "=r"(r[2]), "=r"(r[3]) : "r"(a));
}

__device__ __forceinline__ void ldsm4t(unsigned* r, uint32_t a)
{
    asm volatile("ldmatrix.sync.aligned.m8n8.x4.trans.shared.b16 {%0,%1,%2,%3}, [%4];"
                 : "=r"(r[0]), "=r"(r[1]), "=r"(r[2]), "=r"(r[3]) : "r"(a));
}

__device__ __forceinline__ void cp16(uint32_t s, const void* g)
{
    asm volatile("cp.async.cg.shared.global [%0], [%1], 16;"
                 :: "r"(s), "l"(g) : "memory");
}

// ---------------------------------------------------------------------------
// bf16 MMA GEMM, templated on product count:
//   PROD==3: acc = Ah*Bh + Ah*Bl + Al*Bh  (hi/lo error-compensated split)
//   PROD==1: acc = Ah*Bh                  (plain bf16; lo buffers not loaded)
// BM=BN=128, BK=32, 256 thr, 8 warps (warp tile 32x64), 2-stage cp.async,
// ldmatrix fragments (conflict-free strides 40 / 136 bf16).
// blockIdx.z = split-K slice; EPI 0 writes partial at C + z*M*ldc.
// EPI 2: fused ADMM: v=Vh+Vl; x=Q+v-acc; z=max(x+U-thr,0); U'=U+x-z;
//        vnew = is_last ? z : 2z-U-x; split vnew -> Vh,Vl (bf16).
// ---------------------------------------------------------------------------
#define BSTG  37888
#define BSMEM (2 * BSTG)

template<int EPI, int PROD>
__global__ void __launch_bounds__(256, 2)
bmma_gemm(const __nv_bfloat16* __restrict__ Ah, const __nv_bfloat16* __restrict__ Al,
          const __nv_bfloat16* __restrict__ Bh, const __nv_bfloat16* __restrict__ Bl,
          float* __restrict__ C, int M, int N, int Kslice,
          int lda, int ldb, int ldc,
          const float* __restrict__ Qp, float* __restrict__ Up,
          __nv_bfloat16* __restrict__ Vh, __nv_bfloat16* __restrict__ Vl,
          int is_last)
{
    extern __shared__ char smd[];
    const int tid  = threadIdx.x;
    const int lane = tid & 31, wid = tid >> 5;
    const int wm = (wid & 3) * 32;
    const int wn = (wid >> 2) * 64;
    const int m0 = blockIdx.y * 128, n0 = blockIdx.x * 128;
    const long k0 = (long)blockIdx.z * Kslice;
    const int nk = Kslice >> 5;

    const int aRow = wm + ((lane >> 3) & 1) * 8 + (lane & 7);
    const int aKof = (lane >> 4) * 8;
    const int bRow = ((lane >> 3) & 1) * 8 + (lane & 7);
    const int bNof = (lane >> 4) * 8;

    float c[2][8][4];
#pragma unroll
    for (int i = 0; i < 2; ++i)
#pragma unroll
        for (int j = 0; j < 8; ++j)
#pragma unroll
            for (int q = 0; q < 4; ++q) c[i][j][q] = 0.0f;

    auto load_tile = [&](int kt, int buf) {
        char* base = smd + buf * BSTG;
        const int kb = kt * 32;
#pragma unroll
        for (int cc = 0; cc < 2; ++cc) {        // A: 128 rows x 4 chunks (8 bf16)
            int ch  = tid * 2 + cc;
            int row = ch >> 2, kc = (ch & 3) * 8;
            uint32_t so = (uint32_t)__cvta_generic_to_shared(
                base + (row * 40 + kc) * 2);
            const long go = (long)(m0 + row) * lda + k0 + kb + kc;
            cp16(so, Ah + go);
            if (PROD == 3) cp16(so + 10240, Al + go);
        }
#pragma unroll
        for (int cc = 0; cc < 2; ++cc) {        // B: 32 rows x 16 chunks
            int ch  = tid * 2 + cc;
            int row = ch >> 4, nc = (ch & 15) * 8;
            uint32_t so = (uint32_t)__cvta_generic_to_shared(
                base + 20480 + (row * 136 + nc) * 2);
            const long go = (long)(k0 + kb + row) * ldb + n0 + nc;
            cp16(so, Bh + go);
            if (PROD == 3) cp16(so + 8704, Bl + go);
        }
    };

    load_tile(0, 0);
    asm volatile("cp.async.commit_group;" ::: "memory");

    for (int kt = 0; kt < nk; ++kt) {
        asm volatile("cp.async.wait_group 0;" ::: "memory");
        __syncthreads();
        if (kt + 1 < nk) load_tile(kt + 1, (kt + 1) & 1);
        asm volatile("cp.async.commit_group;" ::: "memory");

        const uint32_t sb = (uint32_t)__cvta_generic_to_shared(smd + (kt & 1) * BSTG);

#pragma unroll
        for (int ks = 0; ks < 2; ++ks) {
            unsigned ah[2][4], al[2][4];
#pragma unroll
            for (int i = 0; i < 2; ++i) {
                uint32_t ad = sb + ((aRow + i * 16) * 40 + ks * 16 + aKof) * 2;
                ldsm4(ah[i], ad);
                if (PROD == 3) ldsm4(al[i], ad + 10240);
            }
#pragma unroll
            for (int ng = 0; ng < 4; ++ng) {
                unsigned bh[4], bl[4];
                uint32_t bd = sb + 20480 +
                              ((bRow + ks * 16) * 136 + wn + ng * 16 + bNof) * 2;
                ldsm4t(bh, bd);
                if (PROD == 3) ldsm4t(bl, bd + 8704);
#pragma unroll
                for (int jj = 0; jj < 2; ++jj) {
                    const int j = ng * 2 + jj;
#pragma unroll
                    for (int i = 0; i < 2; ++i) {
                        mma16(c[i][j], ah[i], bh[jj * 2], bh[jj * 2 + 1]);
                        if (PROD == 3) {
                            mma16(c[i][j], ah[i], bl[jj * 2], bl[jj * 2 + 1]);
                            mma16(c[i][j], al[i], bh[jj * 2], bh[jj * 2 + 1]);
                        }
                    }
                }
            }
        }
    }

    // ---- epilogue ----
    const int gq = lane >> 2, tq = lane & 3;
#pragma unroll
    for (int i = 0; i < 2; ++i) {
        const int r0 = m0 + wm + i * 16 + gq;
#pragma unroll
        for (int j = 0; j < 8; ++j) {
            const int ccn = n0 + wn + j * 8 + 2 * tq;
            if (ccn >= N) continue;
            if (EPI == 0) {
                float* Cz = C + (long)blockIdx.z * (long)M * ldc;
                *(float2*)&Cz[(long)r0 * ldc + ccn] =
                    make_float2(c[i][j][0], c[i][j][1]);
                *(float2*)&Cz[(long)(r0 + 8) * ldc + ccn] =
                    make_float2(c[i][j][2], c[i][j][3]);
            } else {
#pragma unroll
                for (int rr = 0; rr < 2; ++rr) {
                    const long idx = (long)(r0 + rr * 8) * ldc + ccn;
                    float a0 = c[i][j][rr * 2 + 0], a1 = c[i][j][rr * 2 + 1];
                    float2 qv = *(const float2*)&Qp[idx];
                    float2 uv = *(const float2*)&Up[idx];
                    __nv_bfloat162 vh2 = *(const __nv_bfloat162*)&Vh[idx];
                    __nv_bfloat162 vl2 = *(const __nv_bfloat162*)&Vl[idx];
                    float2 un;
                    __nv_bfloat162 nh, nl;
                    {
                        float v = __bfloat162float(vh2.x) + __bfloat162float(vl2.x);
                        float x = qv.x + v - a0;
                        float z = fmaxf(x + uv.x - THR_F, 0.f);
                        un.x = uv.x + x - z;
                        float vn = is_last ? z : (2.f * z - uv.x - x);
                        split_bf16(vn, nh.x, nl.x);
                    }
                    {
                        float v = __bfloat162float(vh2.y) + __bfloat162float(vl2.y);
                        float x = qv.y + v - a1;
                        float z = fmaxf(x + uv.y - THR_F, 0.f);
                        un.y = uv.y + x - z;
                        float vn = is_last ? z : (2.f * z - uv.y - x);
                        split_bf16(vn, nh.y, nl.y);
                    }
                    *(float2*)&Up[idx] = un;
                    *(__nv_bfloat162*)&Vh[idx] = nh;
                    *(__nv_bfloat162*)&Vl[idx] = nl;
                }
            }
        }
    }
}

// ---------------------------------------------------------------------------
// SIMT tiled SGEMM (setup path only -- full fp32 accuracy)
// ---------------------------------------------------------------------------
#define BM 128
#define BN 128
#define BKK 16

template<bool TA, bool TB, int EPI>
__global__ void __launch_bounds__(256, 2)
gemm_kernel(const float* __restrict__ A, const float* __restrict__ B,
            float* __restrict__ C,
            int M, int N, int Kslice, int lda, int ldb, int ldc,
            const float* __restrict__ Qp)
{
    __shared__ float As[BKK][BM + 4];
    __shared__ float Bs[BKK][BN + 4];

    const int tid = threadIdx.x;
    const int tx  = tid & 15;
    const int ty  = tid >> 4;
    const int m0  = blockIdx.y * BM;
    const int n0  = blockIdx.x * BN;

    const long k0 = (long)blockIdx.z * Kslice;
    if (TA) A += k0 * lda; else A += k0;
    if (TB) B += k0;       else B += k0 * ldb;
    if (EPI == 0) C += (long)blockIdx.z * (long)M * ldc;

    float acc[8][8];
#pragma unroll
    for (int i = 0; i < 8; ++i)
#pragma unroll
        for (int j = 0; j < 8; ++j) acc[i][j] = 0.0f;

    const int nk = Kslice / BKK;
#pragma unroll 1
    for (int kt = 0; kt < nk; ++kt) {
        const int kbase = kt * BKK;
        if (!TA) {
#pragma unroll
            for (int p = 0; p < 2; ++p) {
                const int row = p * 64 + (tid >> 2);
                const int c4  = (tid & 3) * 4;
                float4 v = *(const float4*)&A[(long)(m0 + row) * lda + kbase + c4];
                As[c4 + 0][row] = v.x; As[c4 + 1][row] = v.y;
                As[c4 + 2][row] = v.z; As[c4 + 3][row] = v.w;
            }
        } else {
#pragma unroll
            for (int p = 0; p < 2; ++p) {
                const int kr = p * 8 + (tid >> 5);
                const int m4 = (tid & 31) * 4;
                float4 v = *(const float4*)&A[(long)(kbase + kr) * lda + m0 + m4];
                *(float4*)&As[kr][m4] = v;
            }
        }
        if (!TB) {
#pragma unroll
            for (int p = 0; p < 2; ++p) {
                const int kr  = p * 8 + (tid >> 5);
                const int nn4 = (tid & 31) * 4;
                const int gn  = n0 + nn4;
                float4 v = make_float4(0.f, 0.f, 0.f, 0.f);
                if (gn < N) v = *(const float4*)&B[(long)(kbase + kr) * ldb + gn];
                *(float4*)&Bs[kr][nn4] = v;
            }
        } else {
#pragma unroll
            for (int p = 0; p < 2; ++p) {
                const int nrow = p * 64 + (tid >> 2);
                const int c4   = (tid & 3) * 4;
                const int gn   = n0 + nrow;
                float4 v = make_float4(0.f, 0.f, 0.f, 0.f);
                if (gn < N) v = *(const float4*)&B[(long)gn * ldb + kbase + c4];
                Bs[c4 + 0][nrow] = v.x; Bs[c4 + 1][nrow] = v.y;
                Bs[c4 + 2][nrow] = v.z; Bs[c4 + 3][nrow] = v.w;
            }
        }
        __syncthreads();
#pragma unroll
        for (int kk = 0; kk < BKK; ++kk) {
            float a[8], b[8];
            *(float4*)&a[0] = *(const float4*)&As[kk][ty * 4];
            *(float4*)&a[4] = *(const float4*)&As[kk][64 + ty * 4];
            *(float4*)&b[0] = *(const float4*)&Bs[kk][tx * 4];
            *(float4*)&b[4] = *(const float4*)&Bs[kk][64 + tx * 4];
#pragma unroll
            for (int i = 0; i < 8; ++i)
#pragma unroll
                for (int j = 0; j < 8; ++j)
                    acc[i][j] = fmaf(a[i], b[j], acc[i][j]);
        }
        __syncthreads();
    }

    int rows[8];
#pragma unroll
    for (int i = 0; i < 8; ++i)
        rows[i] = m0 + (i < 4 ? ty * 4 + i : 64 + ty * 4 + (i - 4));

#pragma unroll
    for (int i = 0; i < 8; ++i) {
#pragma unroll
        for (int jg = 0; jg < 2; ++jg) {
            const int cn = n0 + jg * 64 + tx * 4;
            if (cn >= N) continue;
            const long idx = (long)rows[i] * ldc + cn;
            float a0 = acc[i][jg * 4 + 0], a1 = acc[i][jg * 4 + 1];
            float a2 = acc[i][jg * 4 + 2], a3 = acc[i][jg * 4 + 3];
            if (EPI == 0) {
                *(float4*)&C[idx] = make_float4(a0, a1, a2, a3);
            } else { // EPI 1: q = (Aty - acc) / rho
                float4 q = *(const float4*)&Qp[idx];
                const float ir = 1.0f / RHO_F;
                *(float4*)&C[idx] = make_float4((q.x - a0) * ir, (q.y - a1) * ir,
                                                (q.z - a2) * ir, (q.w - a3) * ir);
            }
        }
    }
}

// ---------------------------------------------------------------------------
// Reductions / splits
// ---------------------------------------------------------------------------
__global__ void reduce_sum(const float4* __restrict__ P, float4* __restrict__ out,
                           int n4, int S)
{
    int i = blockIdx.x * blockDim.x + threadIdx.x;
    if (i >= n4) return;
    float4 s = P[i];
    for (int k = 1; k < S; ++k) {
        float4 t = P[(long)k * n4 + i];
        s.x += t.x; s.y += t.y; s.z += t.z; s.w += t.w;
    }
    out[i] = s;
}

__global__ void reduce_split_k(const float2* __restrict__ P,
                               __nv_bfloat162* __restrict__ Wh,
                               __nv_bfloat162* __restrict__ Wl,
                               int n2, int S)
{
    int i = blockIdx.x * blockDim.x + threadIdx.x;
    if (i >= n2) return;
    float2 s = P[i];
    for (int k = 1; k < S; ++k) {
        float2 t = P[(long)k * n2 + i];
        s.x += t.x; s.y += t.y;
    }
    __nv_bfloat162 h, l;
    split_bf16(s.x, h.x, l.x);
    split_bf16(s.y, h.y, l.y);
    Wh[i] = h; Wl[i] = l;
}

__global__ void split_mat_bf16(const float2* __restrict__ src,
                               __nv_bfloat162* __restrict__ hi,
                               __nv_bfloat162* __restrict__ lo, long n2)
{
    long i = (long)blockIdx.x * blockDim.x + threadIdx.x;
    if (i >= n2) return;
    float2 v = src[i];
    __nv_bfloat162 h, l;
    split_bf16(v.x, h.x, l.x);
    split_bf16(v.y, h.y, l.y);
    hi[i] = h; lo[i] = l;
}

__global__ void reduce_G(const float* __restrict__ P, float* __restrict__ G, int S)
{
    int i = blockIdx.x * blockDim.x + threadIdx.x;
    if (i >= DM * DM) return;
    float s = 0.f;
    for (int k = 0; k < S; ++k) s += P[(long)k * DM * DM + i];
    if ((i / DM) == (i % DM)) s += RHO_F;
    G[i] = s;
}

__global__ void reduce_ns(const float4* __restrict__ P, const float4* __restrict__ Xc,
                          float4* __restrict__ Xn, int n4, int S)
{
    int i = blockIdx.x * blockDim.x + threadIdx.x;
    if (i >= n4) return;
    float4 s = P[i];
    for (int k = 1; k < S; ++k) {
        float4 t = P[(long)k * n4 + i];
        s.x += t.x; s.y += t.y; s.z += t.z; s.w += t.w;
    }
    float4 x = Xc[i];
    Xn[i] = make_float4(2.f * x.x - s.x, 2.f * x.y - s.y,
                        2.f * x.z - s.z, 2.f * x.w - s.w);
}

__global__ void ninf_kernel(const float* __restrict__ G)
{
    __shared__ float sm[DM];
    const int i = threadIdx.x;
    float s = 0.f;
    for (int j = 0; j < DM; ++j) s += fabsf(G[(long)j * DM + i]);
    sm[i] = s;
    __syncthreads();
    for (int o = DM / 2; o > 0; o >>= 1) {
        if (i < o) sm[i] = fmaxf(sm[i], sm[i + o]);
        __syncthreads();
    }
    if (i == 0) g_ninf = sm[0];
}

__global__ void x0_kernel(float* __restrict__ X)
{
    int i = blockIdx.x * blockDim.x + threadIdx.x;
    if (i >= DM * DM) return;
    float c = 2.0f / (RHO_F + g_ninf);
    X[i] = ((i / DM) == (i % DM)) ? c : 0.0f;
}

// ---------------------------------------------------------------------------
// Row-normalize kernels
// ---------------------------------------------------------------------------
__device__ __forceinline__ float block_sum128(float v, float* red)
{
    for (int o = 16; o > 0; o >>= 1) v += __shfl_xor_sync(0xffffffff, v, o);
    if ((threadIdx.x & 31) == 0) red[threadIdx.x >> 5] = v;
    __syncthreads();
    float tot = red[0] + red[1] + red[2] + red[3];
    __syncthreads();
    return tot;
}

__global__ void norm_center_kernel(const float* __restrict__ img,
                                   const float* __restrict__ mean,
                                   float* __restrict__ out)
{
    __shared__ float red[4];
    const int r = blockIdx.x, t = threadIdx.x;
    float4 v = ((const float4*)(img + (long)r * DM))[t];
    float ss = v.x * v.x + v.y * v.y + v.z * v.z + v.w * v.w;
    float inv = 1.0f / fmaxf(sqrtf(block_sum128(ss, red)), EPS_F);
    float4 mv = ((const float4*)mean)[t];
    float4 c = make_float4(v.x * inv - mv.x, v.y * inv - mv.y,
                           v.z * inv - mv.z, v.w * inv - mv.w);
    float ss2 = c.x * c.x + c.y * c.y + c.z * c.z + c.w * c.w;
    float inv2 = 1.0f / fmaxf(sqrtf(block_sum128(ss2, red)), EPS_F);
    ((float4*)(out + (long)r * DM))[t] =
        make_float4(c.x * inv2, c.y * inv2, c.z * inv2, c.w * inv2);
}

__global__ void norm_rows_kernel(const float* __restrict__ in, float* __restrict__ out)
{
    __shared__ float red[4];
    const int r = blockIdx.x, t = threadIdx.x;
    float4 v = ((const float4*)(in + (long)r * DM))[t];
    float ss = v.x * v.x + v.y * v.y + v.z * v.z + v.w * v.w;
    float inv = 1.0f / fmaxf(sqrtf(block_sum128(ss, red)), EPS_F);
    ((float4*)(out + (long)r * DM))[t] =
        make_float4(v.x * inv, v.y * inv, v.z * inv, v.w * inv);
}

__global__ void final_norm_kernel(const float* __restrict__ rec,
                                  const float* __restrict__ mean,
                                  float* __restrict__ out)
{
    __shared__ float red[4];
    const int r = blockIdx.x, t = threadIdx.x;
    float4 v = ((const float4*)(rec + (long)r * DM))[t];
    float ss = v.x * v.x + v.y * v.y + v.z * v.z + v.w * v.w;
    float inv = 1.0f / fmaxf(sqrtf(block_sum128(ss, red)), EPS_F);
    float4 mv = ((const float4*)mean)[t];
    float4 c = make_float4(v.x * inv + mv.x, v.y * inv + mv.y,
                           v.z * inv + mv.z, v.w * inv + mv.w);
    float ss2 = c.x * c.x + c.y * c.y + c.z * c.z + c.w * c.w;
    float inv2 = 1.0f / fmaxf(sqrtf(block_sum128(ss2, red)), EPS_F);
    ((float4*)(out + (long)r * DM))[t] =
        make_float4(c.x * inv2, c.y * inv2, c.z * inv2, c.w * inv2);
}

// ---------------------------------------------------------------------------
// Host orchestration
// ---------------------------------------------------------------------------
extern "C" void kernel_launch(void* const* d_in, const int* in_sizes, int n_in,
                              void* d_out, int out_size)
{
    const float* dImg  = (const float*)d_in[0];
    const float* dTxt  = (const float*)d_in[1];
    const float* dMean = (const float*)d_in[2];
    const float* dDict = (const float*)d_in[3];
    float* outRecon = (float*)d_out;
    float* outTxt   = (float*)d_out + (long)BROWS * DM;

    float *Q, *U, *E, *P, *W, *Y, *G, *XA, *XB, *T;
    __nv_bfloat16 *Vh, *Vl, *Dh, *Dl, *Eh, *El, *Wh, *Wl;
    cudaGetSymbolAddress((void**)&Q,  g_Q);
    cudaGetSymbolAddress((void**)&U,  g_U);
    cudaGetSymbolAddress((void**)&Vh, g_Vh);
    cudaGetSymbolAddress((void**)&Vl, g_Vl);
    cudaGetSymbolAddress((void**)&Dh, g_Dh);
    cudaGetSymbolAddress((void**)&Dl, g_Dl);
    cudaGetSymbolAddress((void**)&E,  g_E);
    cudaGetSymbolAddress((void**)&Eh, g_Eh);
    cudaGetSymbolAddress((void**)&El, g_El);
    cudaGetSymbolAddress((void**)&P,  g_P);
    cudaGetSymbolAddress((void**)&W,  g_W);
    cudaGetSymbolAddress((void**)&Wh, g_Wh);
    cudaGetSymbolAddress((void**)&Wl, g_Wl);
    cudaGetSymbolAddress((void**)&Y,  g_Y);
    cudaGetSymbolAddress((void**)&G,  g_G);
    cudaGetSymbolAddress((void**)&XA, g_XA);
    cudaGetSymbolAddress((void**)&XB, g_XB);
    cudaGetSymbolAddress((void**)&T,  g_T);

    cudaFuncSetAttribute(bmma_gemm<0, 3>, cudaFuncAttributeMaxDynamicSharedMemorySize, BSMEM);
    cudaFuncSetAttribute(bmma_gemm<2, 3>, cudaFuncAttributeMaxDynamicSharedMemorySize, BSMEM);
    cudaFuncSetAttribute(bmma_gemm<0, 1>, cudaFuncAttributeMaxDynamicSharedMemorySize, BSMEM);
    cudaFuncSetAttribute(bmma_gemm<2, 1>, cudaFuncAttributeMaxDynamicSharedMemorySize, BSMEM);

    const int NT = (CDICT + BN - 1) / BN;   // 79 tiles over N=10000
    const int KSsetup = CDICT / 5;          // 2000 (SIMT setup split-K)
    const int KSmma   = CPAD / KSPLIT;      // 2560 (loop split-K, 4 slices)

    // 1) centered inputs + text output
    norm_center_kernel<<<BROWS, 128>>>(dImg, dMean, Y);
    norm_rows_kernel<<<BROWS, 128>>>(dTxt, outTxt);

    // 2) Aty = Y @ D^T  -> Q  (ld = CPAD)
    gemm_kernel<false, true, 0><<<dim3(NT, 8, 1), 256>>>(
        Y, dDict, Q, BROWS, CDICT, DM, DM, DM, CPAD, nullptr);

    // 3) G = D^T D + rho I
    gemm_kernel<true, false, 0><<<dim3(4, 4, 5), 256>>>(
        dDict, dDict, P, DM, DM, KSsetup, DM, DM, DM, nullptr);
    reduce_G<<<(DM * DM + 255) / 256, 256>>>(P, G, 5);

    // 4) Newton-Schulz inverse
    ninf_kernel<<<1, DM>>>(G);
    x0_kernel<<<(DM * DM + 255) / 256, 256>>>(XA);
    float* Xc = XA; float* Xn = XB;
    for (int t = 0; t < NS_ITERS; ++t) {
        gemm_kernel<false, false, 0><<<dim3(4, 4, 4), 256>>>(
            G, Xc, P, DM, DM, DM / 4, DM, DM, DM, nullptr);
        reduce_sum<<<(DM * DM / 4 + 255) / 256, 256>>>(
            (const float4*)P, (float4*)T, DM * DM / 4, 4);
        gemm_kernel<false, false, 0><<<dim3(4, 4, 4), 256>>>(
            Xc, T, P, DM, DM, DM / 4, DM, DM, DM, nullptr);
        reduce_ns<<<(DM * DM / 4 + 255) / 256, 256>>>(
            (const float4*)P, (const float4*)Xc, (float4*)Xn, DM * DM / 4, 4);
        float* tmp = Xc; Xc = Xn; Xn = tmp;
    }

    // 5) E = G^{-1} @ D^T  (ld = CPAD; pad cols zeroed)
    cudaMemsetAsync(E, 0, sizeof(float) * (size_t)DM * CPAD, 0);
    gemm_kernel<false, true, 0><<<dim3(NT, 4, 1), 256>>>(
        Xc, dDict, E, DM, CDICT, DM, DM, DM, CPAD, nullptr);

    // bf16 splits of D [CPAD x 512] and E [512 x CPAD]
    cudaMemsetAsync(Dh, 0, sizeof(__nv_bfloat16) * (size_t)CPAD * DM, 0);
    cudaMemsetAsync(Dl, 0, sizeof(__nv_bfloat16) * (size_t)CPAD * DM, 0);
    split_mat_bf16<<<(int)(((long)CDICT * DM / 2 + 255) / 256), 256>>>(
        (const float2*)dDict, (__nv_bfloat162*)Dh, (__nv_bfloat162*)Dl,
        (long)CDICT * DM / 2);
    split_mat_bf16<<<(int)(((long)DM * CPAD / 2 + 255) / 256), 256>>>(
        (const float2*)E, (__nv_bfloat162*)Eh, (__nv_bfloat162*)El,
        (long)DM * CPAD / 2);

    // 6) q = (Aty - (Aty @ D) @ E) / rho  (fp32 SIMT, in place on Q)
    gemm_kernel<false, false, 0><<<dim3(4, 8, 5), 256>>>(
        Q, dDict, P, BROWS, DM, KSsetup, CPAD, DM, DM, nullptr);
    reduce_sum<<<(BROWS * DM / 4 + 255) / 256, 256>>>(
        (const float4*)P, (float4*)W, BROWS * DM / 4, 5);
    gemm_kernel<false, false, 1><<<dim3(NT, 8, 1), 256>>>(
        W, E, Q, BROWS, CDICT, DM, DM, CPAD, CPAD, Q);

    // 7) ADMM loop: hybrid precision schedule.
    //    iters [0, CHEAP_ITERS): 1-product bf16 (self-correcting phase)
    //    iters [CHEAP_ITERS, 100): 3-product split (polish to fp32-grade)
    cudaMemsetAsync(Vh, 0, sizeof(__nv_bfloat16) * (size_t)BROWS * CPAD, 0);
    cudaMemsetAsync(Vl, 0, sizeof(__nv_bfloat16) * (size_t)BROWS * CPAD, 0);
    cudaMemsetAsync(U,  0, sizeof(float) * (size_t)BROWS * CPAD, 0);
    for (int it = 0; it < ADMM_ITERS; ++it) {
        const int last = (it == ADMM_ITERS - 1) ? 1 : 0;
        if (it < CHEAP_ITERS) {
            bmma_gemm<0, 1><<<dim3(4, 8, KSPLIT), 256, BSMEM>>>(
                Vh, Vl, Dh, Dl, P, BROWS, DM, KSmma, CPAD, DM, DM,
                nullptr, nullptr, nullptr, nullptr, 0);
            reduce_split_k<<<(BROWS * DM / 2 + 255) / 256, 256>>>(
                (const float2*)P, (__nv_bfloat162*)Wh, (__nv_bfloat162*)Wl,
                BROWS * DM / 2, KSPLIT);
            bmma_gemm<2, 1><<<dim3(NT, 8, 1), 256, BSMEM>>>(
                Wh, Wl, Eh, El, nullptr, BROWS, CDICT, DM, DM, CPAD, CPAD,
                Q, U, Vh, Vl, last);
        } else {
            bmma_gemm<0, 3><<<dim3(4, 8, KSPLIT), 256, BSMEM>>>(
                Vh, Vl, Dh, Dl, P, BROWS, DM, KSmma, CPAD, DM, DM,
                nullptr, nullptr, nullptr, nullptr, 0);
            reduce_split_k<<<(BROWS * DM / 2 + 255) / 256, 256>>>(
                (const float2*)P, (__nv_bfloat162*)Wh, (__nv_bfloat162*)Wl,
                BROWS * DM / 2, KSPLIT);
            bmma_gemm<2, 3><<<dim3(NT, 8, 1), 256, BSMEM>>>(
                Wh, Wl, Eh, El, nullptr, BROWS, CDICT, DM, DM, CPAD, CPAD,
                Q, U, Vh, Vl, last);
        }
    }

    // 8) recon = normalize(normalize(z @ D) + mean)   (z in Vh/Vl; accurate)
    bmma_gemm<0, 3><<<dim3(4, 8, KSPLIT), 256, BSMEM>>>(
        Vh, Vl, Dh, Dl, P, BROWS, DM, KSmma, CPAD, DM, DM,
        nullptr, nullptr, nullptr, nullptr, 0);
    reduce_sum<<<(BROWS * DM / 4 + 255) / 256, 256>>>(
        (const float4*)P, (float4*)W, BROWS * DM / 4, KSPLIT);
    final_norm_kernel<<<BROWS, 128>>>(W, dMean, outRecon);
}

// round 10
// speedup vs baseline: 3.5419x; 1.0544x over previous
#include <cuda_runtime.h>
#include <cuda_bf16.h>
#include <math.h>
#include <stdint.h>

// ---------------------------------------------------------------------------
// Problem constants
// ---------------------------------------------------------------------------
#define BROWS 1024      // batch
#define CDICT 10000     // dictionary atoms
#define CPAD  10240     // padded dict dim: divisible by 128
#define DM    512       // embedding dim
#define RHO_F 5.0f
#define THR_F 0.002f    // lam / rho
#define EPS_F 1e-12f
#define ADMM_ITERS 100
#define CHEAP_ITERS 75  // 1-product bf16 iters; remainder 3-product polish
#define NS_ITERS 9
#define KSPLIT 4        // loop split-K: 128 CTAs <= 148 SMs (balanced)
#define PSLICES 5

// ---------------------------------------------------------------------------
// Scratch (static device globals -- no cudaMalloc allowed)
// ---------------------------------------------------------------------------
__device__ float          g_Q  [(size_t)BROWS * CPAD];  // Aty, then q (ld=CPAD)
__device__ float          g_U  [(size_t)BROWS * CPAD];  // u
__device__ __nv_bfloat16  g_Vh [(size_t)BROWS * CPAD];  // bf16-hi of v
__device__ __nv_bfloat16  g_Vl [(size_t)BROWS * CPAD];  // bf16-lo of v
__device__ __nv_bfloat16  g_Th [(size_t)BROWS * CPAD];  // Aty split hi (setup)
__device__ __nv_bfloat16  g_Tl [(size_t)BROWS * CPAD];  // Aty split lo (setup)
__device__ __nv_bfloat16  g_Dh [(size_t)CPAD * DM];     // dict hi [CPAD x 512]
__device__ __nv_bfloat16  g_Dl [(size_t)CPAD * DM];
__device__ __nv_bfloat16  g_DTh[(size_t)DM * CPAD];     // D^T hi [512 x CPAD]
__device__ __nv_bfloat16  g_DTl[(size_t)DM * CPAD];
__device__ float          g_E  [(size_t)DM * CPAD];     // E = G^{-1} D^T (fp32)
__device__ __nv_bfloat16  g_Eh [(size_t)DM * CPAD];
__device__ __nv_bfloat16  g_El [(size_t)DM * CPAD];
__device__ float          g_P  [(size_t)PSLICES * BROWS * DM];
__device__ float          g_W  [(size_t)BROWS * DM];
__device__ __nv_bfloat16  g_Wh [(size_t)BROWS * DM];
__device__ __nv_bfloat16  g_Wl [(size_t)BROWS * DM];
__device__ float          g_Y  [(size_t)BROWS * DM];
__device__ __nv_bfloat16  g_Yh [(size_t)BROWS * DM];
__device__ __nv_bfloat16  g_Yl [(size_t)BROWS * DM];
__device__ float g_G [DM * DM];
__device__ float g_XA[DM * DM];
__device__ float g_XB[DM * DM];
__device__ float g_T [DM * DM];
__device__ float g_ninf;

// ---------------------------------------------------------------------------
// helpers
// ---------------------------------------------------------------------------
__device__ __forceinline__ void split_bf16(float v, __nv_bfloat16& h, __nv_bfloat16& l)
{
    h = __float2bfloat16_rn(v);
    l = __float2bfloat16_rn(v - __bfloat162float(h));
}

__device__ __forceinline__ void mma16(float* c, const unsigned* a,
                                      unsigned b0, unsigned b1)
{
    asm volatile(
        "mma.sync.aligned.m16n8k16.row.col.f32.bf16.bf16.f32 "
        "{%0,%1,%2,%3}, {%4,%5,%6,%7}, {%8,%9}, {%0,%1,%2,%3};"
        : "+f"(c[0]), "+f"(c[1]), "+f"(c[2]), "+f"(c[3])
        : "r"(a[0]), "r"(a[1]), "r"(a[2]), "r"(a[3]), "r"(b0), "r"(b1));
}

__device__ __forceinline__ void ldsm4(unsigned* r, uint32_t a)
{
    asm volatile("ldmatrix.sync.aligned.m8n8.x4.shared.b16 {%0,%1,%2,%3}, [%4];"
                 : "=r"(r[0]), "=r"(r[1]), "=r"(r[2]), "=r"(r[3]) : "r"(a));
}

__device__ __forceinline__ void ldsm4t(unsigned* r, uint32_t a)
{
    asm volatile("ldmatrix.sync.aligned.m8n8.x4.trans.shared.b16 {%0,%1,%2,%3}, [%4];"
                 : "=r"(r[0]), "=r"(r[1]), "=r"(r[2]), "=r"(r[3]) : "r"(a));
}

__device__ __forceinline__ void cp16(uint32_t s, const void* g)
{
    asm volatile("cp.async.cg.shared.global [%0], [%1], 16;"
                 :: "r"(s), "l"(g) : "memory");
}

// ---------------------------------------------------------------------------
// bf16 MMA GEMM, templated on product count and epilogue:
//   PROD==3: acc = Ah*Bh + Ah*Bl + Al*Bh       PROD==1: acc = Ah*Bh
// EPI 0: plain partial store at C + z*M*ldc (split-K)
// EPI 1: q = (Qp - acc)/rho -> C (fp32)                      [setup]
// EPI 2: full ADMM: v=Vh+Vl, fp32 Q; writes U, Vh, Vl        [polish]
// EPI 3: cheap ADMM: v=Vh, fp32 Q; writes U, Vh; Vl iff flag [cheap]
// BM=BN=128, BK=32, 256 thr, 8 warps (32x64 warp tile), 2-stage cp.async,
// ldmatrix fragments (conflict-free strides 40 / 136 bf16).
// ---------------------------------------------------------------------------
#define BSTG  37888
#define BSMEM (2 * BSTG)

template<int EPI, int PROD>
__global__ void __launch_bounds__(256, 2)
bmma_gemm(const __nv_bfloat16* __restrict__ Ah, const __nv_bfloat16* __restrict__ Al,
          const __nv_bfloat16* __restrict__ Bh, const __nv_bfloat16* __restrict__ Bl,
          float* __restrict__ C, int M, int N, int Kslice,
          int lda, int ldb, int ldc,
          const float* __restrict__ Qp, float* __restrict__ Up,
          __nv_bfloat16* __restrict__ Vh, __nv_bfloat16* __restrict__ Vl,
          int flag)
{
    extern __shared__ char smd[];
    const int tid  = threadIdx.x;
    const int lane = tid & 31, wid = tid >> 5;
    const int wm = (wid & 3) * 32;
    const int wn = (wid >> 2) * 64;
    const int m0 = blockIdx.y * 128, n0 = blockIdx.x * 128;
    const long k0 = (long)blockIdx.z * Kslice;
    const int nk = Kslice >> 5;

    const int aRow = wm + ((lane >> 3) & 1) * 8 + (lane & 7);
    const int aKof = (lane >> 4) * 8;
    const int bRow = ((lane >> 3) & 1) * 8 + (lane & 7);
    const int bNof = (lane >> 4) * 8;

    float c[2][8][4];
#pragma unroll
    for (int i = 0; i < 2; ++i)
#pragma unroll
        for (int j = 0; j < 8; ++j)
#pragma unroll
            for (int q = 0; q < 4; ++q) c[i][j][q] = 0.0f;

    auto load_tile = [&](int kt, int buf) {
        char* base = smd + buf * BSTG;
        const int kb = kt * 32;
#pragma unroll
        for (int cc = 0; cc < 2; ++cc) {        // A: 128 rows x 4 chunks (8 bf16)
            int ch  = tid * 2 + cc;
            int row = ch >> 2, kc = (ch & 3) * 8;
            uint32_t so = (uint32_t)__cvta_generic_to_shared(
                base + (row * 40 + kc) * 2);
            const long go = (long)(m0 + row) * lda + k0 + kb + kc;
            cp16(so, Ah + go);
            if (PROD == 3) cp16(so + 10240, Al + go);
        }
#pragma unroll
        for (int cc = 0; cc < 2; ++cc) {        // B: 32 rows x 16 chunks
            int ch  = tid * 2 + cc;
            int row = ch >> 4, nc = (ch & 15) * 8;
            uint32_t so = (uint32_t)__cvta_generic_to_shared(
                base + 20480 + (row * 136 + nc) * 2);
            const long go = (long)(k0 + kb + row) * ldb + n0 + nc;
            cp16(so, Bh + go);
            if (PROD == 3) cp16(so + 8704, Bl + go);
        }
    };

    load_tile(0, 0);
    asm volatile("cp.async.commit_group;" ::: "memory");

    for (int kt = 0; kt < nk; ++kt) {
        asm volatile("cp.async.wait_group 0;" ::: "memory");
        __syncthreads();
        if (kt + 1 < nk) load_tile(kt + 1, (kt + 1) & 1);
        asm volatile("cp.async.commit_group;" ::: "memory");

        const uint32_t sb = (uint32_t)__cvta_generic_to_shared(smd + (kt & 1) * BSTG);

#pragma unroll
        for (int ks = 0; ks < 2; ++ks) {
            unsigned ah[2][4], al[2][4];
#pragma unroll
            for (int i = 0; i < 2; ++i) {
                uint32_t ad = sb + ((aRow + i * 16) * 40 + ks * 16 + aKof) * 2;
                ldsm4(ah[i], ad);
                if (PROD == 3) ldsm4(al[i], ad + 10240);
            }
#pragma unroll
            for (int ng = 0; ng < 4; ++ng) {
                unsigned bh[4], bl[4];
                uint32_t bd = sb + 20480 +
                              ((bRow + ks * 16) * 136 + wn + ng * 16 + bNof) * 2;
                ldsm4t(bh, bd);
                if (PROD == 3) ldsm4t(bl, bd + 8704);
#pragma unroll
                for (int jj = 0; jj < 2; ++jj) {
                    const int j = ng * 2 + jj;
#pragma unroll
                    for (int i = 0; i < 2; ++i) {
                        mma16(c[i][j], ah[i], bh[jj * 2], bh[jj * 2 + 1]);
                        if (PROD == 3) {
                            mma16(c[i][j], ah[i], bl[jj * 2], bl[jj * 2 + 1]);
                            mma16(c[i][j], al[i], bh[jj * 2], bh[jj * 2 + 1]);
                        }
                    }
                }
            }
        }
    }

    // ---- epilogue ----
    const int gq = lane >> 2, tq = lane & 3;
#pragma unroll
    for (int i = 0; i < 2; ++i) {
        const int r0 = m0 + wm + i * 16 + gq;
#pragma unroll
        for (int j = 0; j < 8; ++j) {
            const int ccn = n0 + wn + j * 8 + 2 * tq;
            if (ccn >= N) continue;
            if (EPI == 0) {
                float* Cz = C + (long)blockIdx.z * (long)M * ldc;
                *(float2*)&Cz[(long)r0 * ldc + ccn] =
                    make_float2(c[i][j][0], c[i][j][1]);
                *(float2*)&Cz[(long)(r0 + 8) * ldc + ccn] =
                    make_float2(c[i][j][2], c[i][j][3]);
            } else if (EPI == 1) {
#pragma unroll
                for (int rr = 0; rr < 2; ++rr) {
                    const long idx = (long)(r0 + rr * 8) * ldc + ccn;
                    const float ir = 1.0f / RHO_F;
                    float2 qv = *(const float2*)&Qp[idx];
                    *(float2*)&C[idx] = make_float2(
                        (qv.x - c[i][j][rr * 2 + 0]) * ir,
                        (qv.y - c[i][j][rr * 2 + 1]) * ir);
                }
            } else if (EPI == 2) {
#pragma unroll
                for (int rr = 0; rr < 2; ++rr) {
                    const long idx = (long)(r0 + rr * 8) * ldc + ccn;
                    float a0 = c[i][j][rr * 2 + 0], a1 = c[i][j][rr * 2 + 1];
                    float2 qv = *(const float2*)&Qp[idx];
                    float2 uv = *(const float2*)&Up[idx];
                    __nv_bfloat162 vh2 = *(const __nv_bfloat162*)&Vh[idx];
                    __nv_bfloat162 vl2 = *(const __nv_bfloat162*)&Vl[idx];
                    float2 un;
                    __nv_bfloat162 nh, nl;
                    {
                        float v = __bfloat162float(vh2.x) + __bfloat162float(vl2.x);
                        float x = qv.x + v - a0;
                        float z = fmaxf(x + uv.x - THR_F, 0.f);
                        un.x = uv.x + x - z;
                        float vn = flag ? z : (2.f * z - uv.x - x);
                        split_bf16(vn, nh.x, nl.x);
                    }
                    {
                        float v = __bfloat162float(vh2.y) + __bfloat162float(vl2.y);
                        float x = qv.y + v - a1;
                        float z = fmaxf(x + uv.y - THR_F, 0.f);
                        un.y = uv.y + x - z;
                        float vn = flag ? z : (2.f * z - uv.y - x);
                        split_bf16(vn, nh.y, nl.y);
                    }
                    *(float2*)&Up[idx] = un;
                    *(__nv_bfloat162*)&Vh[idx] = nh;
                    *(__nv_bfloat162*)&Vl[idx] = nl;
                }
            } else { // EPI == 3: cheap ADMM (v = Vh only, fp32 q; Vl iff flag)
#pragma unroll
                for (int rr = 0; rr < 2; ++rr) {
                    const long idx = (long)(r0 + rr * 8) * ldc + ccn;
                    float a0 = c[i][j][rr * 2 + 0], a1 = c[i][j][rr * 2 + 1];
                    float2 qv = *(const float2*)&Qp[idx];
                    float2 uv = *(const float2*)&Up[idx];
                    __nv_bfloat162 vh2 = *(const __nv_bfloat162*)&Vh[idx];
                    float2 un;
                    __nv_bfloat162 nh, nl;
                    {
                        float x = qv.x + __bfloat162float(vh2.x) - a0;
                        float z = fmaxf(x + uv.x - THR_F, 0.f);
                        un.x = uv.x + x - z;
                        float vn = 2.f * z - uv.x - x;
                        split_bf16(vn, nh.x, nl.x);
                    }
                    {
                        float x = qv.y + __bfloat162float(vh2.y) - a1;
                        float z = fmaxf(x + uv.y - THR_F, 0.f);
                        un.y = uv.y + x - z;
                        float vn = 2.f * z - uv.y - x;
                        split_bf16(vn, nh.y, nl.y);
                    }
                    *(float2*)&Up[idx] = un;
                    *(__nv_bfloat162*)&Vh[idx] = nh;
                    if (flag) *(__nv_bfloat162*)&Vl[idx] = nl;
                }
            }
        }
    }
}

// ---------------------------------------------------------------------------
// SIMT tiled SGEMM (setup path: G, NS, E -- full fp32 accuracy)
// ---------------------------------------------------------------------------
#define BM 128
#define BN 128
#define BKK 16

template<bool TA, bool TB>
__global__ void __launch_bounds__(256, 2)
gemm_kernel(const float* __restrict__ A, const float* __restrict__ B,
            float* __restrict__ C,
            int M, int N, int Kslice, int lda, int ldb, int ldc)
{
    __shared__ float As[BKK][BM + 4];
    __shared__ float Bs[BKK][BN + 4];

    const int tid = threadIdx.x;
    const int tx  = tid & 15;
    const int ty  = tid >> 4;
    const int m0  = blockIdx.y * BM;
    const int n0  = blockIdx.x * BN;

    const long k0 = (long)blockIdx.z * Kslice;
    if (TA) A += k0 * lda; else A += k0;
    if (TB) B += k0;       else B += k0 * ldb;
    C += (long)blockIdx.z * (long)M * ldc;

    float acc[8][8];
#pragma unroll
    for (int i = 0; i < 8; ++i)
#pragma unroll
        for (int j = 0; j < 8; ++j) acc[i][j] = 0.0f;

    const int nk = Kslice / BKK;
#pragma unroll 1
    for (int kt = 0; kt < nk; ++kt) {
        const int kbase = kt * BKK;
        if (!TA) {
#pragma unroll
            for (int p = 0; p < 2; ++p) {
                const int row = p * 64 + (tid >> 2);
                const int c4  = (tid & 3) * 4;
                float4 v = *(const float4*)&A[(long)(m0 + row) * lda + kbase + c4];
                As[c4 + 0][row] = v.x; As[c4 + 1][row] = v.y;
                As[c4 + 2][row] = v.z; As[c4 + 3][row] = v.w;
            }
        } else {
#pragma unroll
            for (int p = 0; p < 2; ++p) {
                const int kr = p * 8 + (tid >> 5);
                const int m4 = (tid & 31) * 4;
                float4 v = *(const float4*)&A[(long)(kbase + kr) * lda + m0 + m4];
                *(float4*)&As[kr][m4] = v;
            }
        }
        if (!TB) {
#pragma unroll
            for (int p = 0; p < 2; ++p) {
                const int kr  = p * 8 + (tid >> 5);
                const int nn4 = (tid & 31) * 4;
                const int gn  = n0 + nn4;
                float4 v = make_float4(0.f, 0.f, 0.f, 0.f);
                if (gn < N) v = *(const float4*)&B[(long)(kbase + kr) * ldb + gn];
                *(float4*)&Bs[kr][nn4] = v;
            }
        } else {
#pragma unroll
            for (int p = 0; p < 2; ++p) {
                const int nrow = p * 64 + (tid >> 2);
                const int c4   = (tid & 3) * 4;
                const int gn   = n0 + nrow;
                float4 v = make_float4(0.f, 0.f, 0.f, 0.f);
                if (gn < N) v = *(const float4*)&B[(long)gn * ldb + kbase + c4];
                Bs[c4 + 0][nrow] = v.x; Bs[c4 + 1][nrow] = v.y;
                Bs[c4 + 2][nrow] = v.z; Bs[c4 + 3][nrow] = v.w;
            }
        }
        __syncthreads();
#pragma unroll
        for (int kk = 0; kk < BKK; ++kk) {
            float a[8], b[8];
            *(float4*)&a[0] = *(const float4*)&As[kk][ty * 4];
            *(float4*)&a[4] = *(const float4*)&As[kk][64 + ty * 4];
            *(float4*)&b[0] = *(const float4*)&Bs[kk][tx * 4];
            *(float4*)&b[4] = *(const float4*)&Bs[kk][64 + tx * 4];
#pragma unroll
            for (int i = 0; i < 8; ++i)
#pragma unroll
                for (int j = 0; j < 8; ++j)
                    acc[i][j] = fmaf(a[i], b[j], acc[i][j]);
        }
        __syncthreads();
    }

    int rows[8];
#pragma unroll
    for (int i = 0; i < 8; ++i)
        rows[i] = m0 + (i < 4 ? ty * 4 + i : 64 + ty * 4 + (i - 4));

#pragma unroll
    for (int i = 0; i < 8; ++i) {
#pragma unroll
        for (int jg = 0; jg < 2; ++jg) {
            const int cn = n0 + jg * 64 + tx * 4;
            if (cn >= N) continue;
            const long idx = (long)rows[i] * ldc + cn;
            *(float4*)&C[idx] = make_float4(acc[i][jg * 4 + 0], acc[i][jg * 4 + 1],
                                            acc[i][jg * 4 + 2], acc[i][jg * 4 + 3]);
        }
    }
}

// ---------------------------------------------------------------------------
// Transpose + bf16 split: out[i*ldo + j] = split(src[j*lds + i]), i<R, j<C
// ---------------------------------------------------------------------------
__global__ void trans_split_kernel(const float* __restrict__ src, int lds,
                                   __nv_bfloat16* __restrict__ dh,
                                   __nv_bfloat16* __restrict__ dl,
                                   int ldo, int R, int C)
{
    __shared__ float t[32][33];
    const int i0 = blockIdx.x * 32;
    const int j0 = blockIdx.y * 32;
    const int tx = threadIdx.x, ty = threadIdx.y;
    for (int jj = ty; jj < 32; jj += 8) {
        const int j = j0 + jj, i = i0 + tx;
        float v = 0.f;
        if (j < C && i < R) v = src[(long)j * lds + i];
        t[jj][tx] = v;
    }
    __syncthreads();
    for (int ii = ty; ii < 32; ii += 8) {
        const int i = i0 + ii, j = j0 + tx;
        if (i < R && j < C) {
            __nv_bfloat16 h, l;
            split_bf16(t[tx][ii], h, l);
            dh[(long)i * ldo + j] = h;
            dl[(long)i * ldo + j] = l;
        }
    }
}

// ---------------------------------------------------------------------------
// Reductions / splits
// ---------------------------------------------------------------------------
__global__ void reduce_sum(const float4* __restrict__ P, float4* __restrict__ out,
                           int n4, int S)
{
    int i = blockIdx.x * blockDim.x + threadIdx.x;
    if (i >= n4) return;
    float4 s = P[i];
    for (int k = 1; k < S; ++k) {
        float4 t = P[(long)k * n4 + i];
        s.x += t.x; s.y += t.y; s.z += t.z; s.w += t.w;
    }
    out[i] = s;
}

__global__ void reduce_split_hl(const float2* __restrict__ P,
                                __nv_bfloat162* __restrict__ Wh,
                                __nv_bfloat162* __restrict__ Wl,
                                int n2, int S)
{
    int i = blockIdx.x * blockDim.x + threadIdx.x;
    if (i >= n2) return;
    float2 s = P[i];
    for (int k = 1; k < S; ++k) {
        float2 t = P[(long)k * n2 + i];
        s.x += t.x; s.y += t.y;
    }
    __nv_bfloat162 h, l;
    split_bf16(s.x, h.x, l.x);
    split_bf16(s.y, h.y, l.y);
    Wh[i] = h; Wl[i] = l;
}

__global__ void reduce_split_h(const float2* __restrict__ P,
                               __nv_bfloat162* __restrict__ Wh,
                               int n2, int S)
{
    int i = blockIdx.x * blockDim.x + threadIdx.x;
    if (i >= n2) return;
    float2 s = P[i];
    for (int k = 1; k < S; ++k) {
        float2 t = P[(long)k * n2 + i];
        s.x += t.x; s.y += t.y;
    }
    __nv_bfloat162 h;
    h.x = __float2bfloat16_rn(s.x);
    h.y = __float2bfloat16_rn(s.y);
    Wh[i] = h;
}

__global__ void split_mat_bf16(const float2* __restrict__ src,
                               __nv_bfloat162* __restrict__ hi,
                               __nv_bfloat162* __restrict__ lo, long n2)
{
    long i = (long)blockIdx.x * blockDim.x + threadIdx.x;
    if (i >= n2) return;
    float2 v = src[i];
    __nv_bfloat162 h, l;
    split_bf16(v.x, h.x, l.x);
    split_bf16(v.y, h.y, l.y);
    hi[i] = h; lo[i] = l;
}

__global__ void reduce_G(const float* __restrict__ P, float* __restrict__ G, int S)
{
    int i = blockIdx.x * blockDim.x + threadIdx.x;
    if (i >= DM * DM) return;
    float s = 0.f;
    for (int k = 0; k < S; ++k) s += P[(long)k * DM * DM + i];
    if ((i / DM) == (i % DM)) s += RHO_F;
    G[i] = s;
}

__global__ void reduce_ns(const float4* __restrict__ P, const float4* __restrict__ Xc,
                          float4* __restrict__ Xn, int n4, int S)
{
    int i = blockIdx.x * blockDim.x + threadIdx.x;
    if (i >= n4) return;
    float4 s = P[i];
    for (int k = 1; k < S; ++k) {
        float4 t = P[(long)k * n4 + i];
        s.x += t.x; s.y += t.y; s.z += t.z; s.w += t.w;
    }
    float4 x = Xc[i];
    Xn[i] = make_float4(2.f * x.x - s.x, 2.f * x.y - s.y,
                        2.f * x.z - s.z, 2.f * x.w - s.w);
}

__global__ void ninf_kernel(const float* __restrict__ G)
{
    __shared__ float sm[DM];
    const int i = threadIdx.x;
    float s = 0.f;
    for (int j = 0; j < DM; ++j) s += fabsf(G[(long)j * DM + i]);
    sm[i] = s;
    __syncthreads();
    for (int o = DM / 2; o > 0; o >>= 1) {
        if (i < o) sm[i] = fmaxf(sm[i], sm[i + o]);
        __syncthreads();
    }
    if (i == 0) g_ninf = sm[0];
}

__global__ void x0_kernel(float* __restrict__ X)
{
    int i = blockIdx.x * blockDim.x + threadIdx.x;
    if (i >= DM * DM) return;
    float c = 2.0f / (RHO_F + g_ninf);
    X[i] = ((i / DM) == (i % DM)) ? c : 0.0f;
}

// ---------------------------------------------------------------------------
// Row-normalize kernels
// ---------------------------------------------------------------------------
__device__ __forceinline__ float block_sum128(float v, float* red)
{
    for (int o = 16; o > 0; o >>= 1) v += __shfl_xor_sync(0xffffffff, v, o);
    if ((threadIdx.x & 31) == 0) red[threadIdx.x >> 5] = v;
    __syncthreads();
    float tot = red[0] + red[1] + red[2] + red[3];
    __syncthreads();
    return tot;
}

__global__ void norm_center_kernel(const float* __restrict__ img,
                                   const float* __restrict__ mean,
                                   float* __restrict__ out)
{
    __shared__ float red[4];
    const int r = blockIdx.x, t = threadIdx.x;
    float4 v = ((const float4*)(img + (long)r * DM))[t];
    float ss = v.x * v.x + v.y * v.y + v.z * v.z + v.w * v.w;
    float inv = 1.0f / fmaxf(sqrtf(block_sum128(ss, red)), EPS_F);
    float4 mv = ((const float4*)mean)[t];
    float4 c = make_float4(v.x * inv - mv.x, v.y * inv - mv.y,
                           v.z * inv - mv.z, v.w * inv - mv.w);
    float ss2 = c.x * c.x + c.y * c.y + c.z * c.z + c.w * c.w;
    float inv2 = 1.0f / fmaxf(sqrtf(block_sum128(ss2, red)), EPS_F);
    ((float4*)(out + (long)r * DM))[t] =
        make_float4(c.x * inv2, c.y * inv2, c.z * inv2, c.w * inv2);
}

__global__ void norm_rows_kernel(const float* __restrict__ in, float* __restrict__ out)
{
    __shared__ float red[4];
    const int r = blockIdx.x, t = threadIdx.x;
    float4 v = ((const float4*)(in + (long)r * DM))[t];
    float ss = v.x * v.x + v.y * v.y + v.z * v.z + v.w * v.w;
    float inv = 1.0f / fmaxf(sqrtf(block_sum128(ss, red)), EPS_F);
    ((float4*)(out + (long)r * DM))[t] =
        make_float4(v.x * inv, v.y * inv, v.z * inv, v.w * inv);
}

__global__ void final_norm_kernel(const float* __restrict__ rec,
                                  const float* __restrict__ mean,
                                  float* __restrict__ out)
{
    __shared__ float red[4];
    const int r = blockIdx.x, t = threadIdx.x;
    float4 v = ((const float4*)(rec + (long)r * DM))[t];
    float ss = v.x * v.x + v.y * v.y + v.z * v.z + v.w * v.w;
    float inv = 1.0f / fmaxf(sqrtf(block_sum128(ss, red)), EPS_F);
    float4 mv = ((const float4*)mean)[t];
    float4 c = make_float4(v.x * inv + mv.x, v.y * inv + mv.y,
                           v.z * inv + mv.z, v.w * inv + mv.w);
    float ss2 = c.x * c.x + c.y * c.y + c.z * c.z + c.w * c.w;
    float inv2 = 1.0f / fmaxf(sqrtf(block_sum128(ss2, red)), EPS_F);
    ((float4*)(out + (long)r * DM))[t] =
        make_float4(c.x * inv2, c.y * inv2, c.z * inv2, c.w * inv2);
}

// ---------------------------------------------------------------------------
// Host orchestration
// ---------------------------------------------------------------------------
extern "C" void kernel_launch(void* const* d_in, const int* in_sizes, int n_in,
                              void* d_out, int out_size)
{
    const float* dImg  = (const float*)d_in[0];
    const float* dTxt  = (const float*)d_in[1];
    const float* dMean = (const float*)d_in[2];
    const float* dDict = (const float*)d_in[3];
    float* outRecon = (float*)d_out;
    float* outTxt   = (float*)d_out + (long)BROWS * DM;

    float *Q, *U, *E, *P, *W, *Y, *G, *XA, *XB, *T;
    __nv_bfloat16 *Vh, *Vl, *Th, *Tl, *Dh, *Dl, *DTh, *DTl, *Eh, *El,
                  *Wh, *Wl, *Yh, *Yl;
    cudaGetSymbolAddress((void**)&Q,   g_Q);
    cudaGetSymbolAddress((void**)&U,   g_U);
    cudaGetSymbolAddress((void**)&Vh,  g_Vh);
    cudaGetSymbolAddress((void**)&Vl,  g_Vl);
    cudaGetSymbolAddress((void**)&Th,  g_Th);
    cudaGetSymbolAddress((void**)&Tl,  g_Tl);
    cudaGetSymbolAddress((void**)&Dh,  g_Dh);
    cudaGetSymbolAddress((void**)&Dl,  g_Dl);
    cudaGetSymbolAddress((void**)&DTh, g_DTh);
    cudaGetSymbolAddress((void**)&DTl, g_DTl);
    cudaGetSymbolAddress((void**)&E,   g_E);
    cudaGetSymbolAddress((void**)&Eh,  g_Eh);
    cudaGetSymbolAddress((void**)&El,  g_El);
    cudaGetSymbolAddress((void**)&P,   g_P);
    cudaGetSymbolAddress((void**)&W,   g_W);
    cudaGetSymbolAddress((void**)&Wh,  g_Wh);
    cudaGetSymbolAddress((void**)&Wl,  g_Wl);
    cudaGetSymbolAddress((void**)&Y,   g_Y);
    cudaGetSymbolAddress((void**)&Yh,  g_Yh);
    cudaGetSymbolAddress((void**)&Yl,  g_Yl);
    cudaGetSymbolAddress((void**)&G,   g_G);
    cudaGetSymbolAddress((void**)&XA,  g_XA);
    cudaGetSymbolAddress((void**)&XB,  g_XB);
    cudaGetSymbolAddress((void**)&T,   g_T);

    cudaFuncSetAttribute(bmma_gemm<0, 3>, cudaFuncAttributeMaxDynamicSharedMemorySize, BSMEM);
    cudaFuncSetAttribute(bmma_gemm<1, 3>, cudaFuncAttributeMaxDynamicSharedMemorySize, BSMEM);
    cudaFuncSetAttribute(bmma_gemm<2, 3>, cudaFuncAttributeMaxDynamicSharedMemorySize, BSMEM);
    cudaFuncSetAttribute(bmma_gemm<0, 1>, cudaFuncAttributeMaxDynamicSharedMemorySize, BSMEM);
    cudaFuncSetAttribute(bmma_gemm<3, 1>, cudaFuncAttributeMaxDynamicSharedMemorySize, BSMEM);

    const int NT = (CDICT + BN - 1) / BN;   // 79 tiles over N=10000
    const int KSsetup = CDICT / 5;          // 2000 (SIMT setup split-K)
    const int KSmma   = CPAD / KSPLIT;      // 2560 (loop split-K, 4 slices)

    // 0) zero-pad-sensitive buffers
    cudaMemsetAsync(Q,   0, sizeof(float) * (size_t)BROWS * CPAD, 0);
    cudaMemsetAsync(DTh, 0, sizeof(__nv_bfloat16) * (size_t)DM * CPAD, 0);
    cudaMemsetAsync(DTl, 0, sizeof(__nv_bfloat16) * (size_t)DM * CPAD, 0);
    cudaMemsetAsync(Dh,  0, sizeof(__nv_bfloat16) * (size_t)CPAD * DM, 0);
    cudaMemsetAsync(Dl,  0, sizeof(__nv_bfloat16) * (size_t)CPAD * DM, 0);
    cudaMemsetAsync(E,   0, sizeof(float) * (size_t)DM * CPAD, 0);

    // 1) centered inputs + text output; splits of Y and D / D^T
    norm_center_kernel<<<BROWS, 128>>>(dImg, dMean, Y);
    norm_rows_kernel<<<BROWS, 128>>>(dTxt, outTxt);
    split_mat_bf16<<<(BROWS * DM / 2 + 255) / 256, 256>>>(
        (const float2*)Y, (__nv_bfloat162*)Yh, (__nv_bfloat162*)Yl, BROWS * DM / 2);
    split_mat_bf16<<<(int)(((long)CDICT * DM / 2 + 255) / 256), 256>>>(
        (const float2*)dDict, (__nv_bfloat162*)Dh, (__nv_bfloat162*)Dl,
        (long)CDICT * DM / 2);
    trans_split_kernel<<<dim3(16, 313), dim3(32, 8)>>>(
        dDict, DM, DTh, DTl, CPAD, DM, CDICT);

    // 2) Aty = Y @ D^T -> Q (bf16x3 tensor path; Q pads stay zero)
    bmma_gemm<0, 3><<<dim3(NT, 8, 1), 256, BSMEM>>>(
        Yh, Yl, DTh, DTl, Q, BROWS, CDICT, DM, DM, CPAD, CPAD,
        nullptr, nullptr, nullptr, nullptr, 0);

    // 3) G = D^T D + rho I (fp32 SIMT)
    gemm_kernel<true, false><<<dim3(4, 4, 5), 256>>>(
        dDict, dDict, P, DM, DM, KSsetup, DM, DM, DM);
    reduce_G<<<(DM * DM + 255) / 256, 256>>>(P, G, 5);

    // 4) Newton-Schulz inverse (fp32 SIMT)
    ninf_kernel<<<1, DM>>>(G);
    x0_kernel<<<(DM * DM + 255) / 256, 256>>>(XA);
    float* Xc = XA; float* Xn = XB;
    for (int t = 0; t < NS_ITERS; ++t) {
        gemm_kernel<false, false><<<dim3(4, 4, 4), 256>>>(
            G, Xc, P, DM, DM, DM / 4, DM, DM, DM);
        reduce_sum<<<(DM * DM / 4 + 255) / 256, 256>>>(
            (const float4*)P, (float4*)T, DM * DM / 4, 4);
        gemm_kernel<false, false><<<dim3(4, 4, 4), 256>>>(
            Xc, T, P, DM, DM, DM / 4, DM, DM, DM);
        reduce_ns<<<(DM * DM / 4 + 255) / 256, 256>>>(
            (const float4*)P, (const float4*)Xc, (float4*)Xn, DM * DM / 4, 4);
        float* tmp = Xc; Xc = Xn; Xn = tmp;
    }

    // 5) E = G^{-1} @ D^T (fp32 SIMT; ld = CPAD, pads zero) + bf16 split
    gemm_kernel<false, true><<<dim3(NT, 4, 1), 256>>>(
        Xc, dDict, E, DM, CDICT, DM, DM, DM, CPAD);
    split_mat_bf16<<<(int)(((long)DM * CPAD / 2 + 255) / 256), 256>>>(
        (const float2*)E, (__nv_bfloat162*)Eh, (__nv_bfloat162*)El,
        (long)DM * CPAD / 2);

    // 6) q = (Aty - (Aty @ D) @ E) / rho  (bf16x3 tensor path, in place on Q)
    split_mat_bf16<<<(int)(((long)BROWS * CPAD / 2 + 255) / 256), 256>>>(
        (const float2*)Q, (__nv_bfloat162*)Th, (__nv_bfloat162*)Tl,
        (long)BROWS * CPAD / 2);
    bmma_gemm<0, 3><<<dim3(4, 8, KSPLIT), 256, BSMEM>>>(
        Th, Tl, Dh, Dl, P, BROWS, DM, KSmma, CPAD, DM, DM,
        nullptr, nullptr, nullptr, nullptr, 0);
    reduce_split_hl<<<(BROWS * DM / 2 + 255) / 256, 256>>>(
        (const float2*)P, (__nv_bfloat162*)Wh, (__nv_bfloat162*)Wl,
        BROWS * DM / 2, KSPLIT);
    bmma_gemm<1, 3><<<dim3(NT, 8, 1), 256, BSMEM>>>(
        Wh, Wl, Eh, El, Q, BROWS, CDICT, DM, DM, CPAD, CPAD,
        Q, nullptr, nullptr, nullptr, 0);

    // 7) ADMM loop: hybrid precision schedule
    cudaMemsetAsync(Vh, 0, sizeof(__nv_bfloat16) * (size_t)BROWS * CPAD, 0);
    cudaMemsetAsync(Vl, 0, sizeof(__nv_bfloat16) * (size_t)BROWS * CPAD, 0);
    cudaMemsetAsync(U,  0, sizeof(float) * (size_t)BROWS * CPAD, 0);
    for (int it = 0; it < ADMM_ITERS; ++it) {
        if (it < CHEAP_ITERS) {
            const int wl = (it == CHEAP_ITERS - 1) ? 1 : 0;
            bmma_gemm<0, 1><<<dim3(4, 8, KSPLIT), 256, BSMEM>>>(
                Vh, nullptr, Dh, nullptr, P, BROWS, DM, KSmma, CPAD, DM, DM,
                nullptr, nullptr, nullptr, nullptr, 0);
            reduce_split_h<<<(BROWS * DM / 2 + 255) / 256, 256>>>(
                (const float2*)P, (__nv_bfloat162*)Wh, BROWS * DM / 2, KSPLIT);
            bmma_gemm<3, 1><<<dim3(NT, 8, 1), 256, BSMEM>>>(
                Wh, nullptr, Eh, nullptr, nullptr, BROWS, CDICT, DM, DM, CPAD, CPAD,
                Q, U, Vh, Vl, wl);
        } else {
            const int last = (it == ADMM_ITERS - 1) ? 1 : 0;
            bmma_gemm<0, 3><<<dim3(4, 8, KSPLIT), 256, BSMEM>>>(
                Vh, Vl, Dh, Dl, P, BROWS, DM, KSmma, CPAD, DM, DM,
                nullptr, nullptr, nullptr, nullptr, 0);
            reduce_split_hl<<<(BROWS * DM / 2 + 255) / 256, 256>>>(
                (const float2*)P, (__nv_bfloat162*)Wh, (__nv_bfloat162*)Wl,
                BROWS * DM / 2, KSPLIT);
            bmma_gemm<2, 3><<<dim3(NT, 8, 1), 256, BSMEM>>>(
                Wh, Wl, Eh, El, nullptr, BROWS, CDICT, DM, DM, CPAD, CPAD,
                Q, U, Vh, Vl, last);
        }
    }

    // 8) recon = normalize(normalize(z @ D) + mean)   (z in Vh/Vl; accurate)
    bmma_gemm<0, 3><<<dim3(4, 8, KSPLIT), 256, BSMEM>>>(
        Vh, Vl, Dh, Dl, P, BROWS, DM, KSmma, CPAD, DM, DM,
        nullptr, nullptr, nullptr, nullptr, 0);
    reduce_sum<<<(BROWS * DM / 4 + 255) / 256, 256>>>(
        (const float4*)P, (float4*)W, BROWS * DM / 4, KSPLIT);
    final_norm_kernel<<<BROWS, 128>>>(W, dMean, outRecon);
}